// round 5
// baseline (speedup 1.0000x reference)
#include <cuda_runtime.h>
#include <math.h>
#include <stdint.h>

// ---------------------------------------------------------------------------
// Problem constants
// ---------------------------------------------------------------------------
#define T_STEPS 256
#define BATCH   16
#define HID     4096          // H
#define PROJ    512           // P
#define G4H     16384         // 4*H
#define F1      532
#define F2CON   768           // con_x features (1280-512)
#define NBLK    128           // persistent grid size

// ---------------------------------------------------------------------------
// Device scratch (static only — no cudaMalloc allowed)
// ---------------------------------------------------------------------------
__device__ float g_xg1[(size_t)T_STEPS * BATCH * G4H];   // 268 MB
__device__ float g_xg2[(size_t)T_STEPS * BATCH * G4H];   // 268 MB
__device__ float g_Wt1[(size_t)512 * G4H];               // W_hh1^T  [512][16384]
__device__ float g_Wt2[(size_t)1024 * G4H];              // [W_ih2[:,:512]; W_hh2]^T
__device__ float g_Wtr1[(size_t)HID * PROJ];             // W_hr1^T [4096][512]
__device__ float g_Wtr2[(size_t)HID * PROJ];
__device__ float g_out1[(size_t)(T_STEPS + 1) * BATCH * PROJ];  // slot s = h1 entering step s
__device__ float g_out2[(size_t)(T_STEPS + 1) * BATCH * PROJ];
__device__ float g_c1[BATCH * HID];
__device__ float g_c2[BATCH * HID];
__device__ float g_g1h[BATCH * HID];   // o*tanh(c) layer1
__device__ float g_g2h[BATCH * HID];
__device__ int   g_counts[T_STEPS];
__device__ int   g_offsets[T_STEPS + 1];

// grid barrier state (g_arrive self-resets; g_genv monotonic across replays)
__device__ volatile unsigned g_genv;
__device__ unsigned g_arrive;

// ---------------------------------------------------------------------------
// packed f32x2 helpers
// ---------------------------------------------------------------------------
__device__ __forceinline__ unsigned long long pk2(float x, float y) {
    unsigned long long d;
    asm("mov.b64 %0, {%1, %2};" : "=l"(d) : "f"(x), "f"(y));
    return d;
}
__device__ __forceinline__ void fma2(unsigned long long& a, unsigned long long b,
                                     unsigned long long c) {
    asm("fma.rn.f32x2 %0, %1, %2, %0;" : "+l"(a) : "l"(b), "l"(c));
}
__device__ __forceinline__ unsigned long long add2(unsigned long long a,
                                                   unsigned long long b) {
    unsigned long long d;
    asm("add.rn.f32x2 %0, %1, %2;" : "=l"(d) : "l"(a), "l"(b));
    return d;
}
__device__ __forceinline__ float2 up2(unsigned long long d) {
    float2 r;
    asm("mov.b64 {%0, %1}, %2;" : "=f"(r.x), "=f"(r.y) : "l"(d));
    return r;
}
__device__ __forceinline__ float sigf(float x) { return 1.f / (1.f + expf(-x)); }

// ---------------------------------------------------------------------------
// grid-wide barrier (release/acquire via threadfence + gen counter)
// ---------------------------------------------------------------------------
__device__ __forceinline__ void gsync(unsigned& gen) {
    __syncthreads();
    if (threadIdx.x == 0) {
        unsigned next = gen + 1;
        __threadfence();
        if (atomicAdd(&g_arrive, 1u) == (unsigned)(NBLK - 1)) {
            g_arrive = 0u;
            __threadfence();
            g_genv = next;
        } else {
            while (g_genv != next) {}
            __threadfence();
        }
        gen = next;
    }
    __syncthreads();
}

// ---------------------------------------------------------------------------
// init
// ---------------------------------------------------------------------------
__global__ void zero_kernel() {
    const size_t n1 = (size_t)(T_STEPS + 1) * BATCH * PROJ;
    const size_t nc = (size_t)BATCH * HID;
    const size_t tot = 2 * n1 + 2 * nc;
    for (size_t i = (size_t)blockIdx.x * blockDim.x + threadIdx.x; i < tot;
         i += (size_t)gridDim.x * blockDim.x) {
        if (i < n1)               g_out1[i] = 0.f;
        else if (i < 2 * n1)      g_out2[i - n1] = 0.f;
        else if (i < 2 * n1 + nc) g_c1[i - 2 * n1] = 0.f;
        else                      g_c2[i - 2 * n1 - nc] = 0.f;
    }
}

// ---------------------------------------------------------------------------
// Tiled transpose: out[k*rows + j] = in[j*ldin + koff + k]
// ---------------------------------------------------------------------------
__global__ void transpose_k(const float* __restrict__ in, float* __restrict__ out,
                            int rows, int cols, int ldin, int koff) {
    __shared__ float tile[32][33];
    int j0 = blockIdx.x * 32, k0 = blockIdx.y * 32;
    int tx = threadIdx.x, ty = threadIdx.y;
    #pragma unroll
    for (int i = 0; i < 32; i += 8) {
        int j = j0 + ty + i, k = k0 + tx;
        if (j < rows && k < cols) tile[ty + i][tx] = in[(size_t)j * ldin + koff + k];
    }
    __syncthreads();
    #pragma unroll
    for (int i = 0; i < 32; i += 8) {
        int k = k0 + ty + i, j = j0 + tx;
        if (j < rows && k < cols) out[(size_t)k * rows + j] = tile[tx][ty + i];
    }
}

// ---------------------------------------------------------------------------
// SGEMM (NT) with packed f32x2: C[m][n] = A[m]·B[n] + bias[n]
// ---------------------------------------------------------------------------
__global__ void __launch_bounds__(256)
sgemm_nt(const float* __restrict__ A, const float* __restrict__ B,
         const float* __restrict__ bias, float* __restrict__ C,
         int K, int lda, int ldb, int boff) {
    __shared__ float As[16][128];
    __shared__ float Bs[16][128];
    const int tid = threadIdx.x;
    const int tx = tid & 15, ty = tid >> 4;
    const int m0 = blockIdx.y * 128, n0 = blockIdx.x * 128;

    unsigned long long acc[8][4];
    #pragma unroll
    for (int i = 0; i < 8; i++)
        #pragma unroll
        for (int j = 0; j < 4; j++) acc[i][j] = 0ull;

    for (int k0 = 0; k0 < K; k0 += 16) {
        #pragma unroll
        for (int i = 0; i < 8; i++) {
            int e = tid + i * 256;
            int r = e >> 4, c = e & 15;
            As[c][r] = (k0 + c < K) ? A[(size_t)(m0 + r) * lda + k0 + c] : 0.f;
            Bs[c][r] = (k0 + c < K) ? B[(size_t)(n0 + r) * ldb + boff + k0 + c] : 0.f;
        }
        __syncthreads();
        #pragma unroll
        for (int kk = 0; kk < 16; kk++) {
            float a[8];
            *(float4*)&a[0] = *(const float4*)&As[kk][ty * 8];
            *(float4*)&a[4] = *(const float4*)&As[kk][ty * 8 + 4];
            ulonglong2 bq0 = *(const ulonglong2*)&Bs[kk][tx * 8];
            ulonglong2 bq1 = *(const ulonglong2*)&Bs[kk][tx * 8 + 4];
            #pragma unroll
            for (int i = 0; i < 8; i++) {
                unsigned long long av = pk2(a[i], a[i]);
                fma2(acc[i][0], av, bq0.x);
                fma2(acc[i][1], av, bq0.y);
                fma2(acc[i][2], av, bq1.x);
                fma2(acc[i][3], av, bq1.y);
            }
        }
        __syncthreads();
    }
    float bv[8];
    #pragma unroll
    for (int j = 0; j < 8; j++) bv[j] = bias[n0 + tx * 8 + j];
    #pragma unroll
    for (int i = 0; i < 8; i++) {
        size_t rowoff = (size_t)(m0 + ty * 8 + i) * G4H + n0 + tx * 8;
        #pragma unroll
        for (int j = 0; j < 4; j++) {
            float2 v = up2(acc[i][j]);
            C[rowoff + 2 * j]     = v.x + bv[2 * j];
            C[rowoff + 2 * j + 1] = v.y + bv[2 * j + 1];
        }
    }
}

// ---------------------------------------------------------------------------
// Persistent recurrence: phases G1 | P1 | G2 | P2 per step, 3 grid barriers.
// smem layout (floats): hsf [0,16384)  redf [16384,18432)  zbuf [18432,20480)
// P-phase aliases:      gpf [0,2048)   predf [2048,4096)
// ---------------------------------------------------------------------------
template <int KTOT>
__device__ __forceinline__ void gate_phase(
    const float* __restrict__ Wt, const float* __restrict__ xg,
    const float* __restrict__ h1src, const float* __restrict__ h2src,
    float* __restrict__ c, float* __restrict__ gh,
    float* hsf, float* redf, float* zbuf)
{
    const int tid = threadIdx.x;
    // stage h into hsf[k*16 + b] (batch pairs contiguous for f32x2)
    if (KTOT == 512) {
        for (int idx = tid; idx < 512 * 16; idx += 256) {
            int b = idx >> 9, k = idx & 511;
            hsf[k * 16 + b] = h1src[b * 512 + k];
        }
    } else {
        for (int idx = tid; idx < 1024 * 16; idx += 256) {
            int b = idx >> 10, k = idx & 1023;
            hsf[k * 16 + b] = (k < 512) ? h1src[b * 512 + k]
                                        : h2src[b * 512 + (k - 512)];
        }
    }
    __syncthreads();

    const int ksub = tid >> 7;
    const int r    = tid & 127;
    const int gate = r >> 5;
    const int jl   = r & 31;
    const int j0   = blockIdx.x * 32;
    const int row  = gate * HID + j0 + jl;
    const int kh   = KTOT / 2;

    const float* wp = Wt + (size_t)(ksub * kh) * G4H + row;
    const unsigned long long* hp =
        (const unsigned long long*)hsf + (size_t)(ksub * kh) * 8;

    unsigned long long acc[8];
    #pragma unroll
    for (int i = 0; i < 8; i++) acc[i] = 0ull;

    #pragma unroll 4
    for (int k = 0; k < kh; k++) {
        float w = wp[(size_t)k * G4H];
        unsigned long long wv = pk2(w, w);
        const ulonglong2* h4 = (const ulonglong2*)(hp + (size_t)k * 8);
        ulonglong2 ha = h4[0], hb = h4[1], hc = h4[2], hd = h4[3];
        fma2(acc[0], wv, ha.x); fma2(acc[1], wv, ha.y);
        fma2(acc[2], wv, hb.x); fma2(acc[3], wv, hb.y);
        fma2(acc[4], wv, hc.x); fma2(acc[5], wv, hc.y);
        fma2(acc[6], wv, hd.x); fma2(acc[7], wv, hd.y);
    }

    unsigned long long* redu = (unsigned long long*)redf;
    if (ksub == 1) {
        #pragma unroll
        for (int i = 0; i < 8; i++) redu[r * 8 + i] = acc[i];
    }
    __syncthreads();
    if (ksub == 0) {
        #pragma unroll
        for (int bp = 0; bp < 8; bp++) {
            unsigned long long s = add2(acc[bp], redu[r * 8 + bp]);
            float2 v = up2(s);
            float z0 = v.x + xg[(size_t)(2 * bp)     * G4H + row];
            float z1 = v.y + xg[(size_t)(2 * bp + 1) * G4H + row];
            zbuf[gate * 512 + (2 * bp)     * 32 + jl] = z0;
            zbuf[gate * 512 + (2 * bp + 1) * 32 + jl] = z1;
        }
    }
    __syncthreads();

    // cell update: 512 (b,j) items
    for (int it = tid; it < 512; it += 256) {
        int b = it >> 5, j2 = it & 31;
        float zi = zbuf[0 * 512 + b * 32 + j2];
        float zf = zbuf[1 * 512 + b * 32 + j2];
        float zg = zbuf[2 * 512 + b * 32 + j2];
        float zo = zbuf[3 * 512 + b * 32 + j2];
        size_t off = (size_t)b * HID + j0 + j2;
        float cn = sigf(zf) * c[off] + sigf(zi) * tanhf(zg);
        c[off]  = cn;
        gh[off] = sigf(zo) * tanhf(cn);
    }
}

__device__ __forceinline__ void proj_phase(
    const float* __restrict__ gh, const float* __restrict__ Wtr,
    float* __restrict__ hout, float* gpf, float* predf)
{
    const int tid = threadIdx.x;
    const int pt = blockIdx.x & 3;
    const int kc = blockIdx.x >> 2;      // 0..31
    const int p0 = pt * 128;
    const int kb = kc * 128;

    // stage gh chunk [16][128] -> gpf[k*16 + b]; L1-bypass (gh overwritten each step)
    for (int idx = tid; idx < 2048; idx += 256) {
        int b = idx >> 7, k = idx & 127;
        gpf[k * 16 + b] = __ldcg(gh + (size_t)b * HID + kb + k);
    }
    __syncthreads();

    const int ks = tid >> 7;
    const int pl = tid & 127;
    const float* wp = Wtr + (size_t)(kb + ks * 64) * PROJ + p0 + pl;
    const unsigned long long* gp =
        (const unsigned long long*)gpf + (size_t)(ks * 64) * 8;

    unsigned long long acc[8];
    #pragma unroll
    for (int i = 0; i < 8; i++) acc[i] = 0ull;

    #pragma unroll 4
    for (int k = 0; k < 64; k++) {
        float w = wp[(size_t)k * PROJ];
        unsigned long long wv = pk2(w, w);
        const ulonglong2* h4 = (const ulonglong2*)(gp + (size_t)k * 8);
        ulonglong2 ha = h4[0], hb = h4[1], hc = h4[2], hd = h4[3];
        fma2(acc[0], wv, ha.x); fma2(acc[1], wv, ha.y);
        fma2(acc[2], wv, hb.x); fma2(acc[3], wv, hb.y);
        fma2(acc[4], wv, hc.x); fma2(acc[5], wv, hc.y);
        fma2(acc[6], wv, hd.x); fma2(acc[7], wv, hd.y);
    }

    unsigned long long* pr = (unsigned long long*)predf;
    if (ks == 1) {
        #pragma unroll
        for (int i = 0; i < 8; i++) pr[pl * 8 + i] = acc[i];
    }
    __syncthreads();
    if (ks == 0) {
        #pragma unroll
        for (int bp = 0; bp < 8; bp++) {
            unsigned long long s = add2(acc[bp], pr[pl * 8 + bp]);
            float2 v = up2(s);
            atomicAdd(hout + (size_t)(2 * bp)     * PROJ + p0 + pl, v.x);
            atomicAdd(hout + (size_t)(2 * bp + 1) * PROJ + p0 + pl, v.y);
        }
    }
}

__global__ void __launch_bounds__(256, 1) recurrence_kernel() {
    extern __shared__ float smem[];
    float* hsf   = smem;
    float* redf  = smem + 16384;
    float* zbuf  = smem + 16384 + 2048;
    float* gpf   = smem;
    float* predf = smem + 2048;

    unsigned gen = g_genv;   // stable: release only after all blocks arrive

    for (int t = 0; t < T_STEPS; t++) {
        gate_phase<512>(g_Wt1, g_xg1 + (size_t)t * BATCH * G4H,
                        g_out1 + (size_t)t * (BATCH * PROJ), nullptr,
                        g_c1, g_g1h, hsf, redf, zbuf);
        gsync(gen);
        proj_phase(g_g1h, g_Wtr1, g_out1 + (size_t)(t + 1) * (BATCH * PROJ),
                   gpf, predf);
        gsync(gen);
        gate_phase<1024>(g_Wt2, g_xg2 + (size_t)t * BATCH * G4H,
                         g_out1 + (size_t)(t + 1) * (BATCH * PROJ),
                         g_out2 + (size_t)t * (BATCH * PROJ),
                         g_c2, g_g2h, hsf, redf, zbuf);
        gsync(gen);
        proj_phase(g_g2h, g_Wtr2, g_out2 + (size_t)(t + 1) * (BATCH * PROJ),
                   gpf, predf);
        // P2(t) is independent of G1(t+1); block-local sync suffices for smem reuse.
        __syncthreads();
    }
}

// ---------------------------------------------------------------------------
// Packed-sequence bookkeeping
// ---------------------------------------------------------------------------
__global__ void counts_kernel(const int* __restrict__ lens) {
    int t = threadIdx.x;
    int c = 0;
    #pragma unroll
    for (int b = 0; b < BATCH; b++) c += (lens[b] > t) ? 1 : 0;
    g_counts[t] = c;
    __syncthreads();
    if (t == 0) {
        int s = 0;
        for (int i = 0; i < T_STEPS; i++) { g_offsets[i] = s; s += g_counts[i]; }
        g_offsets[T_STEPS] = s;
    }
}

// ---------------------------------------------------------------------------
// Heads: one warp per packed token
// ---------------------------------------------------------------------------
__global__ void __launch_bounds__(512) heads_kernel(
    const float* __restrict__ Wp, const float* __restrict__ bp,
    const float* __restrict__ Wa, const float* __restrict__ ba,
    float* __restrict__ out, int total) {
    const int t = blockIdx.x;
    const int w = threadIdx.x >> 5;
    const int lane = threadIdx.x & 31;
    if (w >= g_counts[t]) return;
    const int b = w;
    const int tok = g_offsets[t] + b;

    const float* o1 = g_out1 + (size_t)(t + 1) * (BATCH * PROJ) + (size_t)b * PROJ;
    const float* o2 = g_out2 + (size_t)(t + 1) * (BATCH * PROJ) + (size_t)b * PROJ;
    float v[16];
    #pragma unroll
    for (int i = 0; i < 16; i++) v[i] = o1[lane + 32 * i] + o2[lane + 32 * i];

    __shared__ float sp[16][20];
    __shared__ float sa[16][20];
    #pragma unroll
    for (int o = 0; o < 20; o++) {
        float s1 = 0.f, s2 = 0.f;
        #pragma unroll
        for (int i = 0; i < 16; i++) {
            float x = v[i];
            s1 = fmaf(x, Wp[o * PROJ + lane + 32 * i], s1);
            s2 = fmaf(x, Wa[o * PROJ + lane + 32 * i], s2);
        }
        #pragma unroll
        for (int off = 16; off; off >>= 1) {
            s1 += __shfl_xor_sync(0xffffffffu, s1, off);
            s2 += __shfl_xor_sync(0xffffffffu, s2, off);
        }
        if (lane == 0) { sp[w][o] = s1 + bp[o]; sa[w][o] = s2 + ba[o]; }
    }
    __syncwarp();
    if (lane == 0) {
        float m = -1e30f;
        #pragma unroll
        for (int o = 0; o < 20; o++) m = fmaxf(m, sp[w][o]);
        float e[20], sum = 0.f;
        #pragma unroll
        for (int o = 0; o < 20; o++) { e[o] = expf(sp[w][o] - m); sum += e[o]; }
        float inv = 1.f / sum;
        float* aa = out + (size_t)total * 20;
        #pragma unroll
        for (int o = 0; o < 20; o++) {
            out[(size_t)tok * 20 + o] = e[o] * inv;
            aa[(size_t)tok * 20 + o]  = sa[w][o];
        }
    }
}

// ---------------------------------------------------------------------------
// Final states: h1, c1, h2, c2
// ---------------------------------------------------------------------------
__global__ void finalize_kernel(float* __restrict__ out, int total) {
    const size_t base = (size_t)total * 40;
    const int nH = BATCH * PROJ;   // 8192
    const int nC = BATCH * HID;    // 65536
    int idx = blockIdx.x * blockDim.x + threadIdx.x;
    if (idx >= 2 * (nH + nC)) return;
    float v;
    if (idx < nH)                v = g_out1[(size_t)T_STEPS * nH + idx];
    else if (idx < nH + nC)      v = g_c1[idx - nH];
    else if (idx < 2 * nH + nC)  v = g_out2[(size_t)T_STEPS * nH + (idx - nH - nC)];
    else                         v = g_c2[idx - 2 * nH - nC];
    out[base + idx] = v;
}

// ---------------------------------------------------------------------------
// Host launch
// ---------------------------------------------------------------------------
extern "C" void kernel_launch(void* const* d_in, const int* in_sizes, int n_in,
                              void* d_out, int out_size) {
    const float* uncon  = (const float*)d_in[0];
    const float* con    = (const float*)d_in[1];
    const int*   lens   = (const int*)d_in[2];
    const float* W_ih1  = (const float*)d_in[3];
    const float* b1     = (const float*)d_in[4];
    const float* W_hh1  = (const float*)d_in[5];
    const float* W_hr1  = (const float*)d_in[6];
    const float* W_ih2  = (const float*)d_in[7];
    const float* b2     = (const float*)d_in[8];
    const float* W_hh2  = (const float*)d_in[9];
    const float* W_hr2  = (const float*)d_in[10];
    const float* W_pssm = (const float*)d_in[11];
    const float* b_pssm = (const float*)d_in[12];
    const float* W_aa   = (const float*)d_in[13];
    const float* b_aa   = (const float*)d_in[14];
    float* out = (float*)d_out;

    const int total = (out_size - 2 * (BATCH * PROJ + BATCH * HID)) / 40;

    float *p_Wt1, *p_Wt2, *p_Wtr1, *p_Wtr2, *p_xg1, *p_xg2;
    cudaGetSymbolAddress((void**)&p_Wt1,  g_Wt1);
    cudaGetSymbolAddress((void**)&p_Wt2,  g_Wt2);
    cudaGetSymbolAddress((void**)&p_Wtr1, g_Wtr1);
    cudaGetSymbolAddress((void**)&p_Wtr2, g_Wtr2);
    cudaGetSymbolAddress((void**)&p_xg1,  g_xg1);
    cudaGetSymbolAddress((void**)&p_xg2,  g_xg2);

    // persistent kernel needs >48KB dynamic smem
    cudaFuncSetAttribute(recurrence_kernel,
                         cudaFuncAttributeMaxDynamicSharedMemorySize, 81920);

    // init rings / states
    zero_kernel<<<2048, 256>>>();

    // weight transposes
    dim3 tb(32, 8);
    transpose_k<<<dim3(G4H / 32, 512 / 32), tb>>>(W_hh1, p_Wt1, G4H, 512, 512, 0);
    transpose_k<<<dim3(G4H / 32, 512 / 32), tb>>>(W_ih2, p_Wt2, G4H, 512, 1280, 0);
    transpose_k<<<dim3(G4H / 32, 512 / 32), tb>>>(W_hh2, p_Wt2 + (size_t)512 * G4H,
                                                  G4H, 512, 512, 0);
    transpose_k<<<dim3(512 / 32, HID / 32), tb>>>(W_hr1, p_Wtr1, 512, HID, HID, 0);
    transpose_k<<<dim3(512 / 32, HID / 32), tb>>>(W_hr2, p_Wtr2, 512, HID, HID, 0);

    // Phase A: input-gate GEMMs (bias folded in)
    sgemm_nt<<<dim3(G4H / 128, (T_STEPS * BATCH) / 128), 256>>>(
        uncon, W_ih1, b1, p_xg1, F1, F1, F1, 0);
    sgemm_nt<<<dim3(G4H / 128, (T_STEPS * BATCH) / 128), 256>>>(
        con, W_ih2, b2, p_xg2, F2CON, F2CON, 1280, 512);

    // Phase B: persistent recurrence (single launch, 128 co-resident blocks)
    recurrence_kernel<<<NBLK, 256, 81920>>>();

    // Phase C: packing + heads + final states
    counts_kernel<<<1, 256>>>(lens);
    heads_kernel<<<T_STEPS, 512>>>(W_pssm, b_pssm, W_aa, b_aa, out, total);
    finalize_kernel<<<(2 * (BATCH * PROJ + BATCH * HID) + 255) / 256, 256>>>(out, total);
}

// round 6
// speedup vs baseline: 1.6267x; 1.6267x over previous
#include <cuda_runtime.h>
#include <math.h>
#include <stdint.h>

// ---------------------------------------------------------------------------
// Problem constants
// ---------------------------------------------------------------------------
#define T_STEPS 256
#define BATCH   16
#define HID     4096          // H
#define PROJ    512           // P
#define G4H     16384         // 4*H
#define F1      532
#define F2CON   768           // con_x features (1280-512)
#define NBLK    128           // persistent grid size
#define HSTR    20            // padded smem row stride (floats) for h tiles

// dynamic smem layout for the persistent kernel (floats):
//   hsf  [0, 20480)            1024*HSTR    (gate2 max)
//   redu [20480, +6912)        3*128*9 ull  (as floats: 6912)
//   zbuf [27392, +2048)
#define SM_RED_OFF  20480
#define SM_Z_OFF    27392
#define SM_TOTAL_F  29440     // 117760 bytes

// ---------------------------------------------------------------------------
// Device scratch (static only — no cudaMalloc allowed)
// ---------------------------------------------------------------------------
__device__ float g_xg1[(size_t)T_STEPS * BATCH * G4H];   // 268 MB
__device__ float g_xg2[(size_t)T_STEPS * BATCH * G4H];   // 268 MB
__device__ float g_Wt1[(size_t)512 * G4H];               // W_hh1^T  [k][row]
__device__ float g_Wt2[(size_t)1024 * G4H];              // [W_ih2[:,:512]; W_hh2]^T
__device__ float g_Wtr1[(size_t)HID * PROJ];             // W_hr1^T [k][p]
__device__ float g_Wtr2[(size_t)HID * PROJ];
__device__ float g_out1[(size_t)(T_STEPS + 1) * BATCH * PROJ];
__device__ float g_out2[(size_t)(T_STEPS + 1) * BATCH * PROJ];
__device__ float g_c1[BATCH * HID];
__device__ float g_c2[BATCH * HID];
__device__ float g_g1h[BATCH * HID];
__device__ float g_g2h[BATCH * HID];
__device__ int   g_counts[T_STEPS];
__device__ int   g_offsets[T_STEPS + 1];

__device__ volatile unsigned g_genv;   // monotonic across replays
__device__ unsigned g_arrive;          // self-resetting

// ---------------------------------------------------------------------------
// packed f32x2 helpers
// ---------------------------------------------------------------------------
__device__ __forceinline__ unsigned long long pk2(float x, float y) {
    unsigned long long d;
    asm("mov.b64 %0, {%1, %2};" : "=l"(d) : "f"(x), "f"(y));
    return d;
}
__device__ __forceinline__ void fma2(unsigned long long& a, unsigned long long b,
                                     unsigned long long c) {
    asm("fma.rn.f32x2 %0, %1, %2, %0;" : "+l"(a) : "l"(b), "l"(c));
}
__device__ __forceinline__ unsigned long long add2(unsigned long long a,
                                                   unsigned long long b) {
    unsigned long long d;
    asm("add.rn.f32x2 %0, %1, %2;" : "=l"(d) : "l"(a), "l"(b));
    return d;
}
__device__ __forceinline__ float2 up2(unsigned long long d) {
    float2 r;
    asm("mov.b64 {%0, %1}, %2;" : "=f"(r.x), "=f"(r.y) : "l"(d));
    return r;
}
__device__ __forceinline__ float sigf(float x) { return 1.f / (1.f + expf(-x)); }

// ---------------------------------------------------------------------------
// grid-wide barrier
// ---------------------------------------------------------------------------
__device__ __forceinline__ void gsync(unsigned& gen) {
    __syncthreads();
    if (threadIdx.x == 0) {
        unsigned next = gen + 1;
        __threadfence();
        if (atomicAdd(&g_arrive, 1u) == (unsigned)(NBLK - 1)) {
            g_arrive = 0u;
            __threadfence();
            g_genv = next;
        } else {
            while (g_genv != next) { __nanosleep(64); }
            __threadfence();
        }
        gen = next;
    }
    __syncthreads();
}

// ---------------------------------------------------------------------------
// init
// ---------------------------------------------------------------------------
__global__ void zero_kernel() {
    const size_t n1 = (size_t)(T_STEPS + 1) * BATCH * PROJ;
    const size_t nc = (size_t)BATCH * HID;
    const size_t tot = 2 * n1 + 2 * nc;
    for (size_t i = (size_t)blockIdx.x * blockDim.x + threadIdx.x; i < tot;
         i += (size_t)gridDim.x * blockDim.x) {
        if (i < n1)               g_out1[i] = 0.f;
        else if (i < 2 * n1)      g_out2[i - n1] = 0.f;
        else if (i < 2 * n1 + nc) g_c1[i - 2 * n1] = 0.f;
        else                      g_c2[i - 2 * n1 - nc] = 0.f;
    }
}

// ---------------------------------------------------------------------------
// Tiled transpose: out[k*rows + j] = in[j*ldin + koff + k]
// ---------------------------------------------------------------------------
__global__ void transpose_k(const float* __restrict__ in, float* __restrict__ out,
                            int rows, int cols, int ldin, int koff) {
    __shared__ float tile[32][33];
    int j0 = blockIdx.x * 32, k0 = blockIdx.y * 32;
    int tx = threadIdx.x, ty = threadIdx.y;
    #pragma unroll
    for (int i = 0; i < 32; i += 8) {
        int j = j0 + ty + i, k = k0 + tx;
        if (j < rows && k < cols) tile[ty + i][tx] = in[(size_t)j * ldin + koff + k];
    }
    __syncthreads();
    #pragma unroll
    for (int i = 0; i < 32; i += 8) {
        int k = k0 + ty + i, j = j0 + tx;
        if (j < rows && k < cols) out[(size_t)k * rows + j] = tile[tx][ty + i];
    }
}

// ---------------------------------------------------------------------------
// SGEMM (NT) with packed f32x2: C[m][n] = A[m]·B[n] + bias[n]
// ---------------------------------------------------------------------------
__global__ void __launch_bounds__(256)
sgemm_nt(const float* __restrict__ A, const float* __restrict__ B,
         const float* __restrict__ bias, float* __restrict__ C,
         int K, int lda, int ldb, int boff) {
    __shared__ float As[16][128];
    __shared__ float Bs[16][128];
    const int tid = threadIdx.x;
    const int tx = tid & 15, ty = tid >> 4;
    const int m0 = blockIdx.y * 128, n0 = blockIdx.x * 128;

    unsigned long long acc[8][4];
    #pragma unroll
    for (int i = 0; i < 8; i++)
        #pragma unroll
        for (int j = 0; j < 4; j++) acc[i][j] = 0ull;

    for (int k0 = 0; k0 < K; k0 += 16) {
        #pragma unroll
        for (int i = 0; i < 8; i++) {
            int e = tid + i * 256;
            int r = e >> 4, c = e & 15;
            As[c][r] = (k0 + c < K) ? A[(size_t)(m0 + r) * lda + k0 + c] : 0.f;
            Bs[c][r] = (k0 + c < K) ? B[(size_t)(n0 + r) * ldb + boff + k0 + c] : 0.f;
        }
        __syncthreads();
        #pragma unroll
        for (int kk = 0; kk < 16; kk++) {
            float a[8];
            *(float4*)&a[0] = *(const float4*)&As[kk][ty * 8];
            *(float4*)&a[4] = *(const float4*)&As[kk][ty * 8 + 4];
            ulonglong2 bq0 = *(const ulonglong2*)&Bs[kk][tx * 8];
            ulonglong2 bq1 = *(const ulonglong2*)&Bs[kk][tx * 8 + 4];
            #pragma unroll
            for (int i = 0; i < 8; i++) {
                unsigned long long av = pk2(a[i], a[i]);
                fma2(acc[i][0], av, bq0.x);
                fma2(acc[i][1], av, bq0.y);
                fma2(acc[i][2], av, bq1.x);
                fma2(acc[i][3], av, bq1.y);
            }
        }
        __syncthreads();
    }
    float bv[8];
    #pragma unroll
    for (int j = 0; j < 8; j++) bv[j] = bias[n0 + tx * 8 + j];
    #pragma unroll
    for (int i = 0; i < 8; i++) {
        size_t rowoff = (size_t)(m0 + ty * 8 + i) * G4H + n0 + tx * 8;
        #pragma unroll
        for (int j = 0; j < 4; j++) {
            float2 v = up2(acc[i][j]);
            C[rowoff + 2 * j]     = v.x + bv[2 * j];
            C[rowoff + 2 * j + 1] = v.y + bv[2 * j + 1];
        }
    }
}

// ---------------------------------------------------------------------------
// Gate phase: 512 threads. Thread micro-tile = 4 rows x 4 batches.
// ksub = tid>>7 splits K four ways; reduction through padded smem.
// Weight read: LDG.128 over 4 contiguous rows (Wt layout [k][row]).
// ---------------------------------------------------------------------------
template <int KTOT>
__device__ __forceinline__ void gate_phase(
    const float* __restrict__ Wt, const float* __restrict__ xg,
    const float* __restrict__ h1src, const float* __restrict__ h2src,
    float* __restrict__ c, float* __restrict__ gh,
    float* hsf, unsigned long long* redu, float* zbuf)
{
    const int tid = threadIdx.x;

    // ---- stage h into hsf[k*HSTR + b] with conflict-free STS.128 ----
    for (int idx = tid; idx < 4 * KTOT; idx += 512) {
        int bb, k;
        if (KTOT == 512) { bb = idx >> 9;  k = idx & 511;  }
        else             { bb = idx >> 10; k = idx & 1023; }
        int b0 = 4 * bb;
        float4 v;
        if (KTOT == 512) {
            v.x = h1src[(b0 + 0) * PROJ + k];
            v.y = h1src[(b0 + 1) * PROJ + k];
            v.z = h1src[(b0 + 2) * PROJ + k];
            v.w = h1src[(b0 + 3) * PROJ + k];
        } else {
            const float* s = (k < 512) ? (h1src + k) : (h2src + (k - 512));
            v.x = s[(b0 + 0) * PROJ];
            v.y = s[(b0 + 1) * PROJ];
            v.z = s[(b0 + 2) * PROJ];
            v.w = s[(b0 + 3) * PROJ];
        }
        *(float4*)&hsf[k * HSTR + 4 * bb] = v;
    }
    __syncthreads();

    // ---- main GEMM micro-tile ----
    const int ksub = tid >> 7;            // 0..3
    const int r    = tid & 127;
    const int rowg = r >> 2;              // 0..31
    const int bg   = (r & 3) << 2;        // 0,4,8,12
    const int gate = rowg >> 3;           // 0..3
    const int j0   = blockIdx.x * 32;
    const int jg   = (rowg & 7) << 2;     // 0..28
    const int row4 = gate * HID + j0 + jg;
    const int kh   = KTOT / 4;
    const int kbeg = ksub * kh;

    const ulonglong2* wp = (const ulonglong2*)(Wt + (size_t)kbeg * G4H + row4);
    const float* hp = hsf + kbeg * HSTR + bg;

    unsigned long long acc[2][4];
    #pragma unroll
    for (int i = 0; i < 2; i++)
        #pragma unroll
        for (int j = 0; j < 4; j++) acc[i][j] = 0ull;

    #pragma unroll 4
    for (int k = 0; k < kh; k++) {
        ulonglong2 w = wp[(size_t)k * (G4H / 4)];
        float4 h = *(const float4*)(hp + k * HSTR);
        unsigned long long h0 = pk2(h.x, h.x), h1 = pk2(h.y, h.y);
        unsigned long long h2 = pk2(h.z, h.z), h3 = pk2(h.w, h.w);
        fma2(acc[0][0], w.x, h0); fma2(acc[1][0], w.y, h0);
        fma2(acc[0][1], w.x, h1); fma2(acc[1][1], w.y, h1);
        fma2(acc[0][2], w.x, h2); fma2(acc[1][2], w.y, h2);
        fma2(acc[0][3], w.x, h3); fma2(acc[1][3], w.y, h3);
    }

    if (ksub > 0) {
        unsigned long long* dst = redu + (size_t)(ksub - 1) * 1152 + r * 9;
        #pragma unroll
        for (int rp = 0; rp < 2; rp++)
            #pragma unroll
            for (int bi = 0; bi < 4; bi++) dst[rp * 4 + bi] = acc[rp][bi];
    }
    __syncthreads();

    if (ksub == 0) {
        #pragma unroll
        for (int g = 0; g < 3; g++) {
            const unsigned long long* src = redu + (size_t)g * 1152 + r * 9;
            #pragma unroll
            for (int rp = 0; rp < 2; rp++)
                #pragma unroll
                for (int bi = 0; bi < 4; bi++)
                    acc[rp][bi] = add2(acc[rp][bi], src[rp * 4 + bi]);
        }
        #pragma unroll
        for (int bi = 0; bi < 4; bi++) {
            float4 x = *(const float4*)&xg[(size_t)(bg + bi) * G4H + row4];
            float2 a0 = up2(acc[0][bi]);
            float2 a1 = up2(acc[1][bi]);
            float4 z;
            z.x = a0.x + x.x; z.y = a0.y + x.y;
            z.z = a1.x + x.z; z.w = a1.y + x.w;
            *(float4*)&zbuf[gate * 512 + (bg + bi) * 32 + jg] = z;
        }
    }
    __syncthreads();

    // ---- cell update: 512 items, one per thread ----
    {
        int b = tid >> 5, jl = tid & 31;
        float zi = zbuf[0 * 512 + b * 32 + jl];
        float zf = zbuf[1 * 512 + b * 32 + jl];
        float zg = zbuf[2 * 512 + b * 32 + jl];
        float zo = zbuf[3 * 512 + b * 32 + jl];
        size_t off = (size_t)b * HID + j0 + jl;
        float cn = sigf(zf) * c[off] + sigf(zi) * tanhf(zg);
        c[off]  = cn;
        gh[off] = sigf(zo) * tanhf(cn);
    }
}

// ---------------------------------------------------------------------------
// Projection phase: 512 threads, 4-way K split over the block's 128-k chunk.
// blocks: pt = blockIdx.x & 3 (128 p each), kc = blockIdx.x >> 2 (128 k each).
// ---------------------------------------------------------------------------
__device__ __forceinline__ void proj_phase(
    const float* __restrict__ gh, const float* __restrict__ Wtr,
    float* __restrict__ hout, float* gpf, unsigned long long* predu)
{
    const int tid = threadIdx.x;
    const int pt = blockIdx.x & 3;
    const int kc = blockIdx.x >> 2;
    const int p0 = pt * 128, kb = kc * 128;

    // stage gh[16][128] -> gpf[k*HSTR + b]   (512 elements of float4 work)
    {
        int bb = tid >> 7, k = tid & 127;
        int b0 = 4 * bb;
        float4 v;
        v.x = __ldcg(gh + (size_t)(b0 + 0) * HID + kb + k);
        v.y = __ldcg(gh + (size_t)(b0 + 1) * HID + kb + k);
        v.z = __ldcg(gh + (size_t)(b0 + 2) * HID + kb + k);
        v.w = __ldcg(gh + (size_t)(b0 + 3) * HID + kb + k);
        *(float4*)&gpf[k * HSTR + 4 * bb] = v;
    }
    __syncthreads();

    const int ks = tid >> 7, r = tid & 127;
    const int rowg = r >> 2, bg = (r & 3) << 2;
    const int p4 = p0 + rowg * 4;
    const int kbeg = ks * 32;

    const ulonglong2* wp = (const ulonglong2*)(Wtr + (size_t)(kb + kbeg) * PROJ + p4);
    const float* hp = gpf + kbeg * HSTR + bg;

    unsigned long long acc[2][4];
    #pragma unroll
    for (int i = 0; i < 2; i++)
        #pragma unroll
        for (int j = 0; j < 4; j++) acc[i][j] = 0ull;

    #pragma unroll 4
    for (int k = 0; k < 32; k++) {
        ulonglong2 w = wp[(size_t)k * (PROJ / 4)];
        float4 h = *(const float4*)(hp + k * HSTR);
        unsigned long long h0 = pk2(h.x, h.x), h1 = pk2(h.y, h.y);
        unsigned long long h2 = pk2(h.z, h.z), h3 = pk2(h.w, h.w);
        fma2(acc[0][0], w.x, h0); fma2(acc[1][0], w.y, h0);
        fma2(acc[0][1], w.x, h1); fma2(acc[1][1], w.y, h1);
        fma2(acc[0][2], w.x, h2); fma2(acc[1][2], w.y, h2);
        fma2(acc[0][3], w.x, h3); fma2(acc[1][3], w.y, h3);
    }

    if (ks > 0) {
        unsigned long long* dst = predu + (size_t)(ks - 1) * 1152 + r * 9;
        #pragma unroll
        for (int rp = 0; rp < 2; rp++)
            #pragma unroll
            for (int bi = 0; bi < 4; bi++) dst[rp * 4 + bi] = acc[rp][bi];
    }
    __syncthreads();

    if (ks == 0) {
        #pragma unroll
        for (int g = 0; g < 3; g++) {
            const unsigned long long* src = predu + (size_t)g * 1152 + r * 9;
            #pragma unroll
            for (int rp = 0; rp < 2; rp++)
                #pragma unroll
                for (int bi = 0; bi < 4; bi++)
                    acc[rp][bi] = add2(acc[rp][bi], src[rp * 4 + bi]);
        }
        #pragma unroll
        for (int bi = 0; bi < 4; bi++) {
            float2 a0 = up2(acc[0][bi]);
            float2 a1 = up2(acc[1][bi]);
            float* o = hout + (size_t)(bg + bi) * PROJ + p4;
            atomicAdd(o + 0, a0.x);
            atomicAdd(o + 1, a0.y);
            atomicAdd(o + 2, a1.x);
            atomicAdd(o + 3, a1.y);
        }
    }
}

__global__ void __launch_bounds__(512, 1) recurrence_kernel() {
    extern __shared__ float smem[];
    float* hsf  = smem;
    unsigned long long* redu = (unsigned long long*)(smem + SM_RED_OFF);
    float* zbuf = smem + SM_Z_OFF;
    float* gpf  = smem;
    unsigned long long* predu = (unsigned long long*)(smem + 2560);

    unsigned gen = g_genv;

    for (int t = 0; t < T_STEPS; t++) {
        gate_phase<512>(g_Wt1, g_xg1 + (size_t)t * BATCH * G4H,
                        g_out1 + (size_t)t * (BATCH * PROJ), nullptr,
                        g_c1, g_g1h, hsf, redu, zbuf);
        gsync(gen);
        proj_phase(g_g1h, g_Wtr1, g_out1 + (size_t)(t + 1) * (BATCH * PROJ),
                   gpf, predu);
        gsync(gen);
        gate_phase<1024>(g_Wt2, g_xg2 + (size_t)t * BATCH * G4H,
                         g_out1 + (size_t)(t + 1) * (BATCH * PROJ),
                         g_out2 + (size_t)t * (BATCH * PROJ),
                         g_c2, g_g2h, hsf, redu, zbuf);
        gsync(gen);
        proj_phase(g_g2h, g_Wtr2, g_out2 + (size_t)(t + 1) * (BATCH * PROJ),
                   gpf, predu);
        // P2(t) independent of G1(t+1); block-local sync suffices for smem reuse
        __syncthreads();
    }
}

// ---------------------------------------------------------------------------
// Packed-sequence bookkeeping
// ---------------------------------------------------------------------------
__global__ void counts_kernel(const int* __restrict__ lens) {
    int t = threadIdx.x;
    int c = 0;
    #pragma unroll
    for (int b = 0; b < BATCH; b++) c += (lens[b] > t) ? 1 : 0;
    g_counts[t] = c;
    __syncthreads();
    if (t == 0) {
        int s = 0;
        for (int i = 0; i < T_STEPS; i++) { g_offsets[i] = s; s += g_counts[i]; }
        g_offsets[T_STEPS] = s;
    }
}

// ---------------------------------------------------------------------------
// Heads: one warp per packed token
// ---------------------------------------------------------------------------
__global__ void __launch_bounds__(512) heads_kernel(
    const float* __restrict__ Wp, const float* __restrict__ bp,
    const float* __restrict__ Wa, const float* __restrict__ ba,
    float* __restrict__ out, int total) {
    const int t = blockIdx.x;
    const int w = threadIdx.x >> 5;
    const int lane = threadIdx.x & 31;
    if (w >= g_counts[t]) return;
    const int b = w;
    const int tok = g_offsets[t] + b;

    const float* o1 = g_out1 + (size_t)(t + 1) * (BATCH * PROJ) + (size_t)b * PROJ;
    const float* o2 = g_out2 + (size_t)(t + 1) * (BATCH * PROJ) + (size_t)b * PROJ;
    float v[16];
    #pragma unroll
    for (int i = 0; i < 16; i++) v[i] = o1[lane + 32 * i] + o2[lane + 32 * i];

    __shared__ float sp[16][20];
    __shared__ float sa[16][20];
    #pragma unroll
    for (int o = 0; o < 20; o++) {
        float s1 = 0.f, s2 = 0.f;
        #pragma unroll
        for (int i = 0; i < 16; i++) {
            float x = v[i];
            s1 = fmaf(x, Wp[o * PROJ + lane + 32 * i], s1);
            s2 = fmaf(x, Wa[o * PROJ + lane + 32 * i], s2);
        }
        #pragma unroll
        for (int off = 16; off; off >>= 1) {
            s1 += __shfl_xor_sync(0xffffffffu, s1, off);
            s2 += __shfl_xor_sync(0xffffffffu, s2, off);
        }
        if (lane == 0) { sp[w][o] = s1 + bp[o]; sa[w][o] = s2 + ba[o]; }
    }
    __syncwarp();
    if (lane == 0) {
        float m = -1e30f;
        #pragma unroll
        for (int o = 0; o < 20; o++) m = fmaxf(m, sp[w][o]);
        float e[20], sum = 0.f;
        #pragma unroll
        for (int o = 0; o < 20; o++) { e[o] = expf(sp[w][o] - m); sum += e[o]; }
        float inv = 1.f / sum;
        float* aa = out + (size_t)total * 20;
        #pragma unroll
        for (int o = 0; o < 20; o++) {
            out[(size_t)tok * 20 + o] = e[o] * inv;
            aa[(size_t)tok * 20 + o]  = sa[w][o];
        }
    }
}

// ---------------------------------------------------------------------------
// Final states: h1, c1, h2, c2
// ---------------------------------------------------------------------------
__global__ void finalize_kernel(float* __restrict__ out, int total) {
    const size_t base = (size_t)total * 40;
    const int nH = BATCH * PROJ;
    const int nC = BATCH * HID;
    int idx = blockIdx.x * blockDim.x + threadIdx.x;
    if (idx >= 2 * (nH + nC)) return;
    float v;
    if (idx < nH)                v = g_out1[(size_t)T_STEPS * nH + idx];
    else if (idx < nH + nC)      v = g_c1[idx - nH];
    else if (idx < 2 * nH + nC)  v = g_out2[(size_t)T_STEPS * nH + (idx - nH - nC)];
    else                         v = g_c2[idx - 2 * nH - nC];
    out[base + idx] = v;
}

// ---------------------------------------------------------------------------
// Host launch
// ---------------------------------------------------------------------------
extern "C" void kernel_launch(void* const* d_in, const int* in_sizes, int n_in,
                              void* d_out, int out_size) {
    const float* uncon  = (const float*)d_in[0];
    const float* con    = (const float*)d_in[1];
    const int*   lens   = (const int*)d_in[2];
    const float* W_ih1  = (const float*)d_in[3];
    const float* b1     = (const float*)d_in[4];
    const float* W_hh1  = (const float*)d_in[5];
    const float* W_hr1  = (const float*)d_in[6];
    const float* W_ih2  = (const float*)d_in[7];
    const float* b2     = (const float*)d_in[8];
    const float* W_hh2  = (const float*)d_in[9];
    const float* W_hr2  = (const float*)d_in[10];
    const float* W_pssm = (const float*)d_in[11];
    const float* b_pssm = (const float*)d_in[12];
    const float* W_aa   = (const float*)d_in[13];
    const float* b_aa   = (const float*)d_in[14];
    float* out = (float*)d_out;

    const int total = (out_size - 2 * (BATCH * PROJ + BATCH * HID)) / 40;

    float *p_Wt1, *p_Wt2, *p_Wtr1, *p_Wtr2, *p_xg1, *p_xg2;
    cudaGetSymbolAddress((void**)&p_Wt1,  g_Wt1);
    cudaGetSymbolAddress((void**)&p_Wt2,  g_Wt2);
    cudaGetSymbolAddress((void**)&p_Wtr1, g_Wtr1);
    cudaGetSymbolAddress((void**)&p_Wtr2, g_Wtr2);
    cudaGetSymbolAddress((void**)&p_xg1,  g_xg1);
    cudaGetSymbolAddress((void**)&p_xg2,  g_xg2);

    cudaFuncSetAttribute(recurrence_kernel,
                         cudaFuncAttributeMaxDynamicSharedMemorySize,
                         SM_TOTAL_F * 4);

    zero_kernel<<<2048, 256>>>();

    dim3 tb(32, 8);
    transpose_k<<<dim3(G4H / 32, 512 / 32), tb>>>(W_hh1, p_Wt1, G4H, 512, 512, 0);
    transpose_k<<<dim3(G4H / 32, 512 / 32), tb>>>(W_ih2, p_Wt2, G4H, 512, 1280, 0);
    transpose_k<<<dim3(G4H / 32, 512 / 32), tb>>>(W_hh2, p_Wt2 + (size_t)512 * G4H,
                                                  G4H, 512, 512, 0);
    transpose_k<<<dim3(512 / 32, HID / 32), tb>>>(W_hr1, p_Wtr1, 512, HID, HID, 0);
    transpose_k<<<dim3(512 / 32, HID / 32), tb>>>(W_hr2, p_Wtr2, 512, HID, HID, 0);

    sgemm_nt<<<dim3(G4H / 128, (T_STEPS * BATCH) / 128), 256>>>(
        uncon, W_ih1, b1, p_xg1, F1, F1, F1, 0);
    sgemm_nt<<<dim3(G4H / 128, (T_STEPS * BATCH) / 128), 256>>>(
        con, W_ih2, b2, p_xg2, F2CON, F2CON, 1280, 512);

    recurrence_kernel<<<NBLK, 512, SM_TOTAL_F * 4>>>();

    counts_kernel<<<1, 256>>>(lens);
    heads_kernel<<<T_STEPS, 512>>>(W_pssm, b_pssm, W_aa, b_aa, out, total);
    finalize_kernel<<<(2 * (BATCH * PROJ + BATCH * HID) + 255) / 256, 256>>>(out, total);
}

// round 7
// speedup vs baseline: 1.7033x; 1.0471x over previous
#include <cuda_runtime.h>
#include <math.h>
#include <stdint.h>

// ---------------------------------------------------------------------------
// Problem constants
// ---------------------------------------------------------------------------
#define T_STEPS 256
#define BATCH   16
#define HID     4096          // H
#define PROJ    512           // P
#define G4H     16384         // 4*H
#define F1      532
#define F2CON   768           // con_x features (1280-512)
#define NBLK    128           // persistent grid size
#define HSTR    20            // padded smem row stride (floats) for h tiles

// dynamic smem layout for the persistent kernel (floats):
//   hsf  [0, 20480)                 1024*HSTR (gate2 max)  = 81920 B
//   redu2 [20480, +14336)           7*8*64 ull2            = 57344 B
//   zbuf [34816, +2048)                                    =  8192 B
#define SM_RED_OFF_F  20480
#define SM_Z_OFF_F    34816
#define SM_TOTAL_B    147456

// ---------------------------------------------------------------------------
// Device scratch (static only — no cudaMalloc allowed)
// ---------------------------------------------------------------------------
__device__ float g_xg1[(size_t)T_STEPS * BATCH * G4H];   // 268 MB
__device__ float g_xg2[(size_t)T_STEPS * BATCH * G4H];   // 268 MB
__device__ float g_Wt1[(size_t)512 * G4H];               // W_hh1^T  [k][row]
__device__ float g_Wt2[(size_t)1024 * G4H];              // [W_ih2[:,:512]; W_hh2]^T
__device__ float g_Wtr1[(size_t)HID * PROJ];             // W_hr1^T [k][p]
__device__ float g_Wtr2[(size_t)HID * PROJ];
__device__ float g_out1[(size_t)(T_STEPS + 1) * BATCH * PROJ];
__device__ float g_out2[(size_t)(T_STEPS + 1) * BATCH * PROJ];
__device__ float g_c1[BATCH * HID];
__device__ float g_c2[BATCH * HID];
__device__ float g_g1h[BATCH * HID];
__device__ float g_g2h[BATCH * HID];
__device__ int   g_counts[T_STEPS];
__device__ int   g_offsets[T_STEPS + 1];

__device__ volatile unsigned g_genv;   // monotonic across replays
__device__ unsigned g_arrive;          // self-resetting

// ---------------------------------------------------------------------------
// packed f32x2 helpers
// ---------------------------------------------------------------------------
__device__ __forceinline__ unsigned long long pk2(float x, float y) {
    unsigned long long d;
    asm("mov.b64 %0, {%1, %2};" : "=l"(d) : "f"(x), "f"(y));
    return d;
}
__device__ __forceinline__ void fma2(unsigned long long& a, unsigned long long b,
                                     unsigned long long c) {
    asm("fma.rn.f32x2 %0, %1, %2, %0;" : "+l"(a) : "l"(b), "l"(c));
}
__device__ __forceinline__ unsigned long long add2(unsigned long long a,
                                                   unsigned long long b) {
    unsigned long long d;
    asm("add.rn.f32x2 %0, %1, %2;" : "=l"(d) : "l"(a), "l"(b));
    return d;
}
__device__ __forceinline__ float2 up2(unsigned long long d) {
    float2 r;
    asm("mov.b64 {%0, %1}, %2;" : "=f"(r.x), "=f"(r.y) : "l"(d));
    return r;
}
__device__ __forceinline__ float sigf(float x) { return 1.f / (1.f + expf(-x)); }

// ---------------------------------------------------------------------------
// grid-wide barrier (release/acquire via threadfence + gen counter)
// ---------------------------------------------------------------------------
__device__ __forceinline__ void gsync(unsigned& gen) {
    __syncthreads();
    if (threadIdx.x == 0) {
        unsigned next = gen + 1;
        __threadfence();
        if (atomicAdd(&g_arrive, 1u) == (unsigned)(NBLK - 1)) {
            g_arrive = 0u;
            __threadfence();
            g_genv = next;
        } else {
            while (g_genv != next) {}
            __threadfence();
        }
        gen = next;
    }
    __syncthreads();
}

// ---------------------------------------------------------------------------
// init
// ---------------------------------------------------------------------------
__global__ void zero_kernel() {
    const size_t n1 = (size_t)(T_STEPS + 1) * BATCH * PROJ;
    const size_t nc = (size_t)BATCH * HID;
    const size_t tot = 2 * n1 + 2 * nc;
    for (size_t i = (size_t)blockIdx.x * blockDim.x + threadIdx.x; i < tot;
         i += (size_t)gridDim.x * blockDim.x) {
        if (i < n1)               g_out1[i] = 0.f;
        else if (i < 2 * n1)      g_out2[i - n1] = 0.f;
        else if (i < 2 * n1 + nc) g_c1[i - 2 * n1] = 0.f;
        else                      g_c2[i - 2 * n1 - nc] = 0.f;
    }
}

// ---------------------------------------------------------------------------
// Fused transpose of all 5 weight matrices in ONE launch.
// Region table maps blockIdx.x -> (src, dst, rows, cols, ldin, koff).
// out[k*rows + j] = in[j*ldin + koff + k]
// ---------------------------------------------------------------------------
__global__ void transpose_all(const float* __restrict__ W_hh1,
                              const float* __restrict__ W_ih2,
                              const float* __restrict__ W_hh2,
                              const float* __restrict__ W_hr1,
                              const float* __restrict__ W_hr2) {
    __shared__ float tile[32][33];
    int bid = blockIdx.x;
    const float* in;
    float* out;
    int rows, cols, ldin, koff, tix;
    if (bid < 8192)       { in = W_hh1; out = g_Wt1;  rows = G4H; cols = 512;  ldin = 512;  koff = 0; tix = bid; }
    else if (bid < 16384) { in = W_ih2; out = g_Wt2;  rows = G4H; cols = 512;  ldin = 1280; koff = 0; tix = bid - 8192; }
    else if (bid < 24576) { in = W_hh2; out = g_Wt2 + (size_t)512 * G4H;
                                                       rows = G4H; cols = 512;  ldin = 512;  koff = 0; tix = bid - 16384; }
    else if (bid < 26624) { in = W_hr1; out = g_Wtr1; rows = 512; cols = HID;  ldin = HID;  koff = 0; tix = bid - 24576; }
    else                  { in = W_hr2; out = g_Wtr2; rows = 512; cols = HID;  ldin = HID;  koff = 0; tix = bid - 26624; }

    int nbx = rows >> 5;
    int bx = tix % nbx, by = tix / nbx;
    int j0 = bx * 32, k0 = by * 32;
    int tx = threadIdx.x, ty = threadIdx.y;
    #pragma unroll
    for (int i = 0; i < 32; i += 8) {
        int j = j0 + ty + i, k = k0 + tx;
        tile[ty + i][tx] = in[(size_t)j * ldin + koff + k];
    }
    __syncthreads();
    #pragma unroll
    for (int i = 0; i < 32; i += 8) {
        int k = k0 + ty + i, j = j0 + tx;
        out[(size_t)k * rows + j] = tile[tx][ty + i];
    }
}

// ---------------------------------------------------------------------------
// SGEMM (NT), register-prefetch double-buffered, A duplicated in smem:
// C[m][n] = A[m]·B[n] + bias[n]
// ---------------------------------------------------------------------------
__global__ void __launch_bounds__(256)
sgemm_nt(const float* __restrict__ A, const float* __restrict__ B,
         const float* __restrict__ bias, float* __restrict__ C,
         int K, int lda, int ldb, int boff) {
    __shared__ unsigned long long AsD[16][130];  // (a,a) duplicated, padded
    __shared__ float Bs[16][132];                // padded
    const int tid = threadIdx.x;
    const int tx = tid & 15, ty = tid >> 4;
    const int m0 = blockIdx.y * 128, n0 = blockIdx.x * 128;

    unsigned long long acc[8][4];
    #pragma unroll
    for (int i = 0; i < 8; i++)
        #pragma unroll
        for (int j = 0; j < 4; j++) acc[i][j] = 0ull;

    const int rr = tid >> 4;      // 0..15 (r within chunk of 16)
    const int cc = tid & 15;      // 0..15 (k within tile)

    float ar[8], br[8];
    // prefetch tile 0
    #pragma unroll
    for (int i = 0; i < 8; i++) {
        int r = rr + i * 16;
        ar[i] = (cc < K) ? A[(size_t)(m0 + r) * lda + cc] : 0.f;
        br[i] = (cc < K) ? B[(size_t)(n0 + r) * ldb + boff + cc] : 0.f;
    }

    for (int k0 = 0; k0 < K; k0 += 16) {
        // commit prefetched regs to smem
        #pragma unroll
        for (int i = 0; i < 8; i++) {
            int r = rr + i * 16;
            AsD[cc][r] = pk2(ar[i], ar[i]);
            Bs[cc][r]  = br[i];
        }
        __syncthreads();
        // prefetch next tile while computing current
        int kn = k0 + 16;
        if (kn < K) {
            #pragma unroll
            for (int i = 0; i < 8; i++) {
                int r = rr + i * 16;
                ar[i] = (kn + cc < K) ? A[(size_t)(m0 + r) * lda + kn + cc] : 0.f;
                br[i] = (kn + cc < K) ? B[(size_t)(n0 + r) * ldb + boff + kn + cc] : 0.f;
            }
        }
        #pragma unroll
        for (int kk = 0; kk < 16; kk++) {
            unsigned long long ad[8];
            *(ulonglong2*)&ad[0] = *(const ulonglong2*)&AsD[kk][ty * 8];
            *(ulonglong2*)&ad[2] = *(const ulonglong2*)&AsD[kk][ty * 8 + 2];
            *(ulonglong2*)&ad[4] = *(const ulonglong2*)&AsD[kk][ty * 8 + 4];
            *(ulonglong2*)&ad[6] = *(const ulonglong2*)&AsD[kk][ty * 8 + 6];
            ulonglong2 bq0 = *(const ulonglong2*)&Bs[kk][tx * 8];
            ulonglong2 bq1 = *(const ulonglong2*)&Bs[kk][tx * 8 + 4];
            #pragma unroll
            for (int i = 0; i < 8; i++) {
                fma2(acc[i][0], ad[i], bq0.x);
                fma2(acc[i][1], ad[i], bq0.y);
                fma2(acc[i][2], ad[i], bq1.x);
                fma2(acc[i][3], ad[i], bq1.y);
            }
        }
        __syncthreads();
    }
    float bv[8];
    #pragma unroll
    for (int j = 0; j < 8; j++) bv[j] = bias[n0 + tx * 8 + j];
    #pragma unroll
    for (int i = 0; i < 8; i++) {
        size_t rowoff = (size_t)(m0 + ty * 8 + i) * G4H + n0 + tx * 8;
        #pragma unroll
        for (int j = 0; j < 4; j++) {
            float2 v = up2(acc[i][j]);
            C[rowoff + 2 * j]     = v.x + bv[2 * j];
            C[rowoff + 2 * j + 1] = v.y + bv[2 * j + 1];
        }
    }
}

// ---------------------------------------------------------------------------
// Gate phase: 512 threads, 8-way K split, micro-tile 8 rows x 4 batches.
// c-state lives in a register (cref), written to global only on last step.
// ---------------------------------------------------------------------------
template <int KTOT>
__device__ __forceinline__ void gate_phase(
    const float* __restrict__ Wt, const float* __restrict__ xg,
    const float* __restrict__ h1src, const float* __restrict__ h2src,
    float& cref, float* __restrict__ gh, float* __restrict__ cglob, bool last,
    float* hsf, ulonglong2* redu2, float* zbuf)
{
    const int tid = threadIdx.x;

    // ---- stage h into hsf[k*HSTR + b], float4 stores ----
    for (int idx = tid; idx < 4 * KTOT; idx += 512) {
        int bb, k;
        if (KTOT == 512) { bb = idx >> 9;  k = idx & 511;  }
        else             { bb = idx >> 10; k = idx & 1023; }
        int b0 = 4 * bb;
        float4 v;
        if (KTOT == 512) {
            v.x = h1src[(b0 + 0) * PROJ + k];
            v.y = h1src[(b0 + 1) * PROJ + k];
            v.z = h1src[(b0 + 2) * PROJ + k];
            v.w = h1src[(b0 + 3) * PROJ + k];
        } else {
            const float* s = (k < 512) ? (h1src + k) : (h2src + (k - 512));
            v.x = s[(b0 + 0) * PROJ];
            v.y = s[(b0 + 1) * PROJ];
            v.z = s[(b0 + 2) * PROJ];
            v.w = s[(b0 + 3) * PROJ];
        }
        *(float4*)&hsf[k * HSTR + 4 * bb] = v;
    }
    __syncthreads();

    // ---- main GEMM micro-tile: 8 rows x 4 batches per thread ----
    const int ksub = tid >> 6;            // 0..7
    const int r    = tid & 63;            // 0..63
    const int rowg = r >> 2;              // 0..15
    const int bg   = (r & 3) << 2;        // 0,4,8,12
    const int gate = rowg >> 2;           // 0..3
    const int j0   = blockIdx.x * 32;
    const int jj   = (rowg & 3) << 3;     // 0,8,16,24
    const int row8 = gate * HID + j0 + jj;
    const int kh   = KTOT / 8;
    const int kbeg = ksub * kh;

    const ulonglong2* wp = (const ulonglong2*)(Wt + (size_t)kbeg * G4H + row8);
    const float* hp = hsf + (size_t)kbeg * HSTR + bg;

    unsigned long long acc[4][4];         // [rowpair][batch]
    #pragma unroll
    for (int i = 0; i < 4; i++)
        #pragma unroll
        for (int j = 0; j < 4; j++) acc[i][j] = 0ull;

    #pragma unroll 4
    for (int k = 0; k < kh; k++) {
        ulonglong2 wa = wp[(size_t)k * (G4H / 4)];       // rows 0-3
        ulonglong2 wb = wp[(size_t)k * (G4H / 4) + 1];   // rows 4-7
        float4 h = *(const float4*)(hp + k * HSTR);
        unsigned long long h0 = pk2(h.x, h.x), h1 = pk2(h.y, h.y);
        unsigned long long h2 = pk2(h.z, h.z), h3 = pk2(h.w, h.w);
        fma2(acc[0][0], wa.x, h0); fma2(acc[0][1], wa.x, h1);
        fma2(acc[0][2], wa.x, h2); fma2(acc[0][3], wa.x, h3);
        fma2(acc[1][0], wa.y, h0); fma2(acc[1][1], wa.y, h1);
        fma2(acc[1][2], wa.y, h2); fma2(acc[1][3], wa.y, h3);
        fma2(acc[2][0], wb.x, h0); fma2(acc[2][1], wb.x, h1);
        fma2(acc[2][2], wb.x, h2); fma2(acc[2][3], wb.x, h3);
        fma2(acc[3][0], wb.y, h0); fma2(acc[3][1], wb.y, h1);
        fma2(acc[3][2], wb.y, h2); fma2(acc[3][3], wb.y, h3);
    }

    // column-major ull2 reduction buffer: redu2[(g*8 + rp*2 + bh)*64 + r]
    if (ksub > 0) {
        ulonglong2* dst = redu2 + (size_t)(ksub - 1) * 512 + r;
        #pragma unroll
        for (int rp = 0; rp < 4; rp++)
            #pragma unroll
            for (int bh = 0; bh < 2; bh++)
                dst[(rp * 2 + bh) * 64] = make_ulonglong2(acc[rp][2 * bh],
                                                          acc[rp][2 * bh + 1]);
    }
    __syncthreads();

    if (ksub == 0) {
        #pragma unroll
        for (int g = 0; g < 7; g++) {
            const ulonglong2* src = redu2 + (size_t)g * 512 + r;
            #pragma unroll
            for (int rp = 0; rp < 4; rp++)
                #pragma unroll
                for (int bh = 0; bh < 2; bh++) {
                    ulonglong2 v = src[(rp * 2 + bh) * 64];
                    acc[rp][2 * bh]     = add2(acc[rp][2 * bh], v.x);
                    acc[rp][2 * bh + 1] = add2(acc[rp][2 * bh + 1], v.y);
                }
        }
        #pragma unroll
        for (int bi = 0; bi < 4; bi++) {
            const float* xr = xg + (size_t)(bg + bi) * G4H + row8;
            float4 x0 = *(const float4*)xr;
            float4 x1 = *(const float4*)(xr + 4);
            float2 a0 = up2(acc[0][bi]), a1 = up2(acc[1][bi]);
            float2 a2 = up2(acc[2][bi]), a3 = up2(acc[3][bi]);
            float4 z0 = {a0.x + x0.x, a0.y + x0.y, a1.x + x0.z, a1.y + x0.w};
            float4 z1 = {a2.x + x1.x, a2.y + x1.y, a3.x + x1.z, a3.y + x1.w};
            float* zb = &zbuf[gate * 512 + (bg + bi) * 32 + jj];
            *(float4*)zb = z0;
            *(float4*)(zb + 4) = z1;
        }
    }
    __syncthreads();

    // ---- cell update: one (b,j) per thread, c in register ----
    {
        int b = tid >> 5, jl = tid & 31;
        float zi = zbuf[0 * 512 + b * 32 + jl];
        float zf = zbuf[1 * 512 + b * 32 + jl];
        float zg = zbuf[2 * 512 + b * 32 + jl];
        float zo = zbuf[3 * 512 + b * 32 + jl];
        size_t off = (size_t)b * HID + j0 + jl;
        float cn = sigf(zf) * cref + sigf(zi) * tanhf(zg);
        cref = cn;
        gh[off] = sigf(zo) * tanhf(cn);
        if (last) cglob[off] = cn;
    }
}

// ---------------------------------------------------------------------------
// Projection phase: 512 threads, 4-way K split over the block's 128-k chunk.
// ---------------------------------------------------------------------------
__device__ __forceinline__ void proj_phase(
    const float* __restrict__ gh, const float* __restrict__ Wtr,
    float* __restrict__ hout, float* gpf, unsigned long long* predu)
{
    const int tid = threadIdx.x;
    const int pt = blockIdx.x & 3;
    const int kc = blockIdx.x >> 2;
    const int p0 = pt * 128, kb = kc * 128;

    {
        int bb = tid >> 7, k = tid & 127;
        int b0 = 4 * bb;
        float4 v;
        v.x = __ldcg(gh + (size_t)(b0 + 0) * HID + kb + k);
        v.y = __ldcg(gh + (size_t)(b0 + 1) * HID + kb + k);
        v.z = __ldcg(gh + (size_t)(b0 + 2) * HID + kb + k);
        v.w = __ldcg(gh + (size_t)(b0 + 3) * HID + kb + k);
        *(float4*)&gpf[k * HSTR + 4 * bb] = v;
    }
    __syncthreads();

    const int ks = tid >> 7, r = tid & 127;
    const int rowg = r >> 2, bg = (r & 3) << 2;
    const int p4 = p0 + rowg * 4;
    const int kbeg = ks * 32;

    const ulonglong2* wp = (const ulonglong2*)(Wtr + (size_t)(kb + kbeg) * PROJ + p4);
    const float* hp = gpf + kbeg * HSTR + bg;

    unsigned long long acc[2][4];
    #pragma unroll
    for (int i = 0; i < 2; i++)
        #pragma unroll
        for (int j = 0; j < 4; j++) acc[i][j] = 0ull;

    #pragma unroll 4
    for (int k = 0; k < 32; k++) {
        ulonglong2 w = wp[(size_t)k * (PROJ / 4)];
        float4 h = *(const float4*)(hp + k * HSTR);
        unsigned long long h0 = pk2(h.x, h.x), h1 = pk2(h.y, h.y);
        unsigned long long h2 = pk2(h.z, h.z), h3 = pk2(h.w, h.w);
        fma2(acc[0][0], w.x, h0); fma2(acc[1][0], w.y, h0);
        fma2(acc[0][1], w.x, h1); fma2(acc[1][1], w.y, h1);
        fma2(acc[0][2], w.x, h2); fma2(acc[1][2], w.y, h2);
        fma2(acc[0][3], w.x, h3); fma2(acc[1][3], w.y, h3);
    }

    if (ks > 0) {
        unsigned long long* dst = predu + (size_t)(ks - 1) * 1152 + r * 9;
        #pragma unroll
        for (int rp = 0; rp < 2; rp++)
            #pragma unroll
            for (int bi = 0; bi < 4; bi++) dst[rp * 4 + bi] = acc[rp][bi];
    }
    __syncthreads();

    if (ks == 0) {
        #pragma unroll
        for (int g = 0; g < 3; g++) {
            const unsigned long long* src = predu + (size_t)g * 1152 + r * 9;
            #pragma unroll
            for (int rp = 0; rp < 2; rp++)
                #pragma unroll
                for (int bi = 0; bi < 4; bi++)
                    acc[rp][bi] = add2(acc[rp][bi], src[rp * 4 + bi]);
        }
        #pragma unroll
        for (int bi = 0; bi < 4; bi++) {
            float2 a0 = up2(acc[0][bi]);
            float2 a1 = up2(acc[1][bi]);
            float* o = hout + (size_t)(bg + bi) * PROJ + p4;
            atomicAdd(o + 0, a0.x);
            atomicAdd(o + 1, a0.y);
            atomicAdd(o + 2, a1.x);
            atomicAdd(o + 3, a1.y);
        }
    }
}

__global__ void __launch_bounds__(512, 1) recurrence_kernel() {
    extern __shared__ float smem[];
    float* hsf  = smem;
    ulonglong2* redu2 = (ulonglong2*)(smem + SM_RED_OFF_F);
    float* zbuf = smem + SM_Z_OFF_F;
    float* gpf  = smem;
    unsigned long long* predu = (unsigned long long*)(smem + 2560);

    unsigned gen = g_genv;
    float c1r = 0.f, c2r = 0.f;

    for (int t = 0; t < T_STEPS; t++) {
        bool last = (t == T_STEPS - 1);
        gate_phase<512>(g_Wt1, g_xg1 + (size_t)t * BATCH * G4H,
                        g_out1 + (size_t)t * (BATCH * PROJ), nullptr,
                        c1r, g_g1h, g_c1, last, hsf, redu2, zbuf);
        gsync(gen);
        proj_phase(g_g1h, g_Wtr1, g_out1 + (size_t)(t + 1) * (BATCH * PROJ),
                   gpf, predu);
        gsync(gen);
        gate_phase<1024>(g_Wt2, g_xg2 + (size_t)t * BATCH * G4H,
                         g_out1 + (size_t)(t + 1) * (BATCH * PROJ),
                         g_out2 + (size_t)t * (BATCH * PROJ),
                         c2r, g_g2h, g_c2, last, hsf, redu2, zbuf);
        gsync(gen);
        proj_phase(g_g2h, g_Wtr2, g_out2 + (size_t)(t + 1) * (BATCH * PROJ),
                   gpf, predu);
        // P2(t) independent of G1(t+1); block-local sync suffices for smem reuse
        __syncthreads();
    }
}

// ---------------------------------------------------------------------------
// Packed-sequence bookkeeping
// ---------------------------------------------------------------------------
__global__ void counts_kernel(const int* __restrict__ lens) {
    int t = threadIdx.x;
    int c = 0;
    #pragma unroll
    for (int b = 0; b < BATCH; b++) c += (lens[b] > t) ? 1 : 0;
    g_counts[t] = c;
    __syncthreads();
    if (t == 0) {
        int s = 0;
        for (int i = 0; i < T_STEPS; i++) { g_offsets[i] = s; s += g_counts[i]; }
        g_offsets[T_STEPS] = s;
    }
}

// ---------------------------------------------------------------------------
// Heads: one warp per packed token
// ---------------------------------------------------------------------------
__global__ void __launch_bounds__(512) heads_kernel(
    const float* __restrict__ Wp, const float* __restrict__ bp,
    const float* __restrict__ Wa, const float* __restrict__ ba,
    float* __restrict__ out, int total) {
    const int t = blockIdx.x;
    const int w = threadIdx.x >> 5;
    const int lane = threadIdx.x & 31;
    if (w >= g_counts[t]) return;
    const int b = w;
    const int tok = g_offsets[t] + b;

    const float* o1 = g_out1 + (size_t)(t + 1) * (BATCH * PROJ) + (size_t)b * PROJ;
    const float* o2 = g_out2 + (size_t)(t + 1) * (BATCH * PROJ) + (size_t)b * PROJ;
    float v[16];
    #pragma unroll
    for (int i = 0; i < 16; i++) v[i] = o1[lane + 32 * i] + o2[lane + 32 * i];

    __shared__ float sp[16][20];
    __shared__ float sa[16][20];
    #pragma unroll
    for (int o = 0; o < 20; o++) {
        float s1 = 0.f, s2 = 0.f;
        #pragma unroll
        for (int i = 0; i < 16; i++) {
            float x = v[i];
            s1 = fmaf(x, Wp[o * PROJ + lane + 32 * i], s1);
            s2 = fmaf(x, Wa[o * PROJ + lane + 32 * i], s2);
        }
        #pragma unroll
        for (int off = 16; off; off >>= 1) {
            s1 += __shfl_xor_sync(0xffffffffu, s1, off);
            s2 += __shfl_xor_sync(0xffffffffu, s2, off);
        }
        if (lane == 0) { sp[w][o] = s1 + bp[o]; sa[w][o] = s2 + ba[o]; }
    }
    __syncwarp();
    if (lane == 0) {
        float m = -1e30f;
        #pragma unroll
        for (int o = 0; o < 20; o++) m = fmaxf(m, sp[w][o]);
        float e[20], sum = 0.f;
        #pragma unroll
        for (int o = 0; o < 20; o++) { e[o] = expf(sp[w][o] - m); sum += e[o]; }
        float inv = 1.f / sum;
        float* aa = out + (size_t)total * 20;
        #pragma unroll
        for (int o = 0; o < 20; o++) {
            out[(size_t)tok * 20 + o] = e[o] * inv;
            aa[(size_t)tok * 20 + o]  = sa[w][o];
        }
    }
}

// ---------------------------------------------------------------------------
// Final states: h1, c1, h2, c2
// ---------------------------------------------------------------------------
__global__ void finalize_kernel(float* __restrict__ out, int total) {
    const size_t base = (size_t)total * 40;
    const int nH = BATCH * PROJ;
    const int nC = BATCH * HID;
    int idx = blockIdx.x * blockDim.x + threadIdx.x;
    if (idx >= 2 * (nH + nC)) return;
    float v;
    if (idx < nH)                v = g_out1[(size_t)T_STEPS * nH + idx];
    else if (idx < nH + nC)      v = g_c1[idx - nH];
    else if (idx < 2 * nH + nC)  v = g_out2[(size_t)T_STEPS * nH + (idx - nH - nC)];
    else                         v = g_c2[idx - 2 * nH - nC];
    out[base + idx] = v;
}

// ---------------------------------------------------------------------------
// Host launch
// ---------------------------------------------------------------------------
extern "C" void kernel_launch(void* const* d_in, const int* in_sizes, int n_in,
                              void* d_out, int out_size) {
    const float* uncon  = (const float*)d_in[0];
    const float* con    = (const float*)d_in[1];
    const int*   lens   = (const int*)d_in[2];
    const float* W_ih1  = (const float*)d_in[3];
    const float* b1     = (const float*)d_in[4];
    const float* W_hh1  = (const float*)d_in[5];
    const float* W_hr1  = (const float*)d_in[6];
    const float* W_ih2  = (const float*)d_in[7];
    const float* b2     = (const float*)d_in[8];
    const float* W_hh2  = (const float*)d_in[9];
    const float* W_hr2  = (const float*)d_in[10];
    const float* W_pssm = (const float*)d_in[11];
    const float* b_pssm = (const float*)d_in[12];
    const float* W_aa   = (const float*)d_in[13];
    const float* b_aa   = (const float*)d_in[14];
    float* out = (float*)d_out;

    const int total = (out_size - 2 * (BATCH * PROJ + BATCH * HID)) / 40;

    float *p_xg1, *p_xg2;
    cudaGetSymbolAddress((void**)&p_xg1, g_xg1);
    cudaGetSymbolAddress((void**)&p_xg2, g_xg2);

    cudaFuncSetAttribute(recurrence_kernel,
                         cudaFuncAttributeMaxDynamicSharedMemorySize, SM_TOTAL_B);

    // 1: init rings / states
    zero_kernel<<<2048, 256>>>();
    // 2: all weight transposes in one launch
    transpose_all<<<28672, dim3(32, 8)>>>(W_hh1, W_ih2, W_hh2, W_hr1, W_hr2);
    // 3,4: Phase A input-gate GEMMs (bias folded in)
    sgemm_nt<<<dim3(G4H / 128, (T_STEPS * BATCH) / 128), 256>>>(
        uncon, W_ih1, b1, p_xg1, F1, F1, F1, 0);
    sgemm_nt<<<dim3(G4H / 128, (T_STEPS * BATCH) / 128), 256>>>(
        con, W_ih2, b2, p_xg2, F2CON, F2CON, 1280, 512);
    // 5: packed-sequence bookkeeping (independent of recurrence)
    counts_kernel<<<1, 256>>>(lens);
    // 6: persistent recurrence  (ncu -s 5 -c 1 captures THIS launch)
    recurrence_kernel<<<NBLK, 512, SM_TOTAL_B>>>();
    // 7,8: heads + final states
    heads_kernel<<<T_STEPS, 512>>>(W_pssm, b_pssm, W_aa, b_aa, out, total);
    finalize_kernel<<<(2 * (BATCH * PROJ + BATCH * HID) + 255) / 256, 256>>>(out, total);
}

// round 8
// speedup vs baseline: 2.1327x; 1.2521x over previous
#include <cuda_runtime.h>
#include <math.h>
#include <stdint.h>

// ---------------------------------------------------------------------------
// Problem constants
// ---------------------------------------------------------------------------
#define T_STEPS 256
#define BATCH   16
#define HID     4096          // H
#define PROJ    512           // P
#define G4H     16384         // 4*H
#define F1      532
#define F2CON   768           // con_x features (1280-512)
#define NBLK    128           // persistent grid size
#define HSTR    20            // padded smem row stride (floats) for h tiles

// dynamic smem layout for the persistent kernel (floats):
//   hsf   [0, 20480)            1024*HSTR                  = 81920 B
//   redu2 [20480, +14336)       7*512 ull2                 = 57344 B
//   zbuf  [34816, +2048)                                   =  8192 B
// proj aliases: gpf1 [0,2560) gpf2 [2560,5120) predu [5120,+6912)
#define SM_RED_OFF_F  20480
#define SM_Z_OFF_F    34816
#define SM_TOTAL_B    147456

// ---------------------------------------------------------------------------
// Device scratch (static only — no cudaMalloc allowed)
// ---------------------------------------------------------------------------
__device__ float g_xg1[(size_t)T_STEPS * BATCH * G4H];   // 268 MB
__device__ float g_xg2[(size_t)T_STEPS * BATCH * G4H];   // 268 MB
__device__ float g_Wt1[(size_t)512 * G4H];               // W_hh1^T  [k][row]
__device__ float g_Wt2[(size_t)1024 * G4H];              // [W_ih2[:,:512]; W_hh2]^T
__device__ float g_Wtr1[(size_t)HID * PROJ];             // W_hr1^T [k][p]
__device__ float g_Wtr2[(size_t)HID * PROJ];
__device__ float g_out1[(size_t)(T_STEPS + 1) * BATCH * PROJ];
__device__ float g_out2[(size_t)(T_STEPS + 1) * BATCH * PROJ];
__device__ float g_c1[BATCH * HID];
__device__ float g_c2[BATCH * HID];
__device__ float g_g1h[BATCH * HID];
__device__ float g_g2h[BATCH * HID];
__device__ int   g_counts[T_STEPS];
__device__ int   g_offsets[T_STEPS + 1];

__device__ volatile unsigned g_genv;   // monotonic across replays
__device__ unsigned g_arrive;          // self-resetting

// ---------------------------------------------------------------------------
// packed f32x2 helpers
// ---------------------------------------------------------------------------
__device__ __forceinline__ unsigned long long pk2(float x, float y) {
    unsigned long long d;
    asm("mov.b64 %0, {%1, %2};" : "=l"(d) : "f"(x), "f"(y));
    return d;
}
__device__ __forceinline__ void fma2(unsigned long long& a, unsigned long long b,
                                     unsigned long long c) {
    asm("fma.rn.f32x2 %0, %1, %2, %0;" : "+l"(a) : "l"(b), "l"(c));
}
__device__ __forceinline__ unsigned long long add2(unsigned long long a,
                                                   unsigned long long b) {
    unsigned long long d;
    asm("add.rn.f32x2 %0, %1, %2;" : "=l"(d) : "l"(a), "l"(b));
    return d;
}
__device__ __forceinline__ float2 up2(unsigned long long d) {
    float2 r;
    asm("mov.b64 {%0, %1}, %2;" : "=f"(r.x), "=f"(r.y) : "l"(d));
    return r;
}
__device__ __forceinline__ float sigf(float x) { return 1.f / (1.f + expf(-x)); }

// ---------------------------------------------------------------------------
// grid-wide barrier (release/acquire via threadfence + gen counter)
// ---------------------------------------------------------------------------
__device__ __forceinline__ void gsync(unsigned& gen) {
    __syncthreads();
    if (threadIdx.x == 0) {
        unsigned next = gen + 1;
        __threadfence();
        if (atomicAdd(&g_arrive, 1u) == (unsigned)(NBLK - 1)) {
            g_arrive = 0u;
            __threadfence();
            g_genv = next;
        } else {
            while (g_genv != next) {}
            __threadfence();
        }
        gen = next;
    }
    __syncthreads();
}

// ---------------------------------------------------------------------------
// init
// ---------------------------------------------------------------------------
__global__ void zero_kernel() {
    const size_t n1 = (size_t)(T_STEPS + 1) * BATCH * PROJ;
    const size_t nc = (size_t)BATCH * HID;
    const size_t tot = 2 * n1 + 2 * nc;
    for (size_t i = (size_t)blockIdx.x * blockDim.x + threadIdx.x; i < tot;
         i += (size_t)gridDim.x * blockDim.x) {
        if (i < n1)               g_out1[i] = 0.f;
        else if (i < 2 * n1)      g_out2[i - n1] = 0.f;
        else if (i < 2 * n1 + nc) g_c1[i - 2 * n1] = 0.f;
        else                      g_c2[i - 2 * n1 - nc] = 0.f;
    }
}

// ---------------------------------------------------------------------------
// Fused transpose of all 5 weight matrices in ONE launch.
// ---------------------------------------------------------------------------
__global__ void transpose_all(const float* __restrict__ W_hh1,
                              const float* __restrict__ W_ih2,
                              const float* __restrict__ W_hh2,
                              const float* __restrict__ W_hr1,
                              const float* __restrict__ W_hr2) {
    __shared__ float tile[32][33];
    int bid = blockIdx.x;
    const float* in;
    float* out;
    int rows, ldin, tix;
    if (bid < 8192)       { in = W_hh1; out = g_Wt1;  rows = G4H; ldin = 512;  tix = bid; }
    else if (bid < 16384) { in = W_ih2; out = g_Wt2;  rows = G4H; ldin = 1280; tix = bid - 8192; }
    else if (bid < 24576) { in = W_hh2; out = g_Wt2 + (size_t)512 * G4H;
                                                       rows = G4H; ldin = 512;  tix = bid - 16384; }
    else if (bid < 26624) { in = W_hr1; out = g_Wtr1; rows = 512; ldin = HID;  tix = bid - 24576; }
    else                  { in = W_hr2; out = g_Wtr2; rows = 512; ldin = HID;  tix = bid - 26624; }

    int nbx = rows >> 5;
    int bx = tix % nbx, by = tix / nbx;
    int j0 = bx * 32, k0 = by * 32;
    int tx = threadIdx.x, ty = threadIdx.y;
    #pragma unroll
    for (int i = 0; i < 32; i += 8) {
        int j = j0 + ty + i, k = k0 + tx;
        tile[ty + i][tx] = in[(size_t)j * ldin + k];
    }
    __syncthreads();
    #pragma unroll
    for (int i = 0; i < 32; i += 8) {
        int k = k0 + ty + i, j = j0 + tx;
        out[(size_t)k * rows + j] = tile[tx][ty + i];
    }
}

// ---------------------------------------------------------------------------
// SGEMM (NT), register-prefetch double-buffered, A duplicated in smem.
// __launch_bounds__(256,2): cap regs at 128 -> 2 blocks/SM.
// ---------------------------------------------------------------------------
__global__ void __launch_bounds__(256, 2)
sgemm_nt(const float* __restrict__ A, const float* __restrict__ B,
         const float* __restrict__ bias, float* __restrict__ C,
         int K, int lda, int ldb, int boff) {
    __shared__ unsigned long long AsD[16][130];
    __shared__ float Bs[16][132];
    const int tid = threadIdx.x;
    const int tx = tid & 15, ty = tid >> 4;
    const int m0 = blockIdx.y * 128, n0 = blockIdx.x * 128;

    unsigned long long acc[8][4];
    #pragma unroll
    for (int i = 0; i < 8; i++)
        #pragma unroll
        for (int j = 0; j < 4; j++) acc[i][j] = 0ull;

    const int rr = tid >> 4;
    const int cc = tid & 15;

    float ar[8], br[8];
    #pragma unroll
    for (int i = 0; i < 8; i++) {
        int r = rr + i * 16;
        ar[i] = (cc < K) ? A[(size_t)(m0 + r) * lda + cc] : 0.f;
        br[i] = (cc < K) ? B[(size_t)(n0 + r) * ldb + boff + cc] : 0.f;
    }

    for (int k0 = 0; k0 < K; k0 += 16) {
        #pragma unroll
        for (int i = 0; i < 8; i++) {
            int r = rr + i * 16;
            AsD[cc][r] = pk2(ar[i], ar[i]);
            Bs[cc][r]  = br[i];
        }
        __syncthreads();
        int kn = k0 + 16;
        if (kn < K) {
            #pragma unroll
            for (int i = 0; i < 8; i++) {
                int r = rr + i * 16;
                ar[i] = (kn + cc < K) ? A[(size_t)(m0 + r) * lda + kn + cc] : 0.f;
                br[i] = (kn + cc < K) ? B[(size_t)(n0 + r) * ldb + boff + kn + cc] : 0.f;
            }
        }
        #pragma unroll
        for (int kk = 0; kk < 16; kk++) {
            unsigned long long ad[8];
            *(ulonglong2*)&ad[0] = *(const ulonglong2*)&AsD[kk][ty * 8];
            *(ulonglong2*)&ad[2] = *(const ulonglong2*)&AsD[kk][ty * 8 + 2];
            *(ulonglong2*)&ad[4] = *(const ulonglong2*)&AsD[kk][ty * 8 + 4];
            *(ulonglong2*)&ad[6] = *(const ulonglong2*)&AsD[kk][ty * 8 + 6];
            ulonglong2 bq0 = *(const ulonglong2*)&Bs[kk][tx * 8];
            ulonglong2 bq1 = *(const ulonglong2*)&Bs[kk][tx * 8 + 4];
            #pragma unroll
            for (int i = 0; i < 8; i++) {
                fma2(acc[i][0], ad[i], bq0.x);
                fma2(acc[i][1], ad[i], bq0.y);
                fma2(acc[i][2], ad[i], bq1.x);
                fma2(acc[i][3], ad[i], bq1.y);
            }
        }
        __syncthreads();
    }
    float bv[8];
    #pragma unroll
    for (int j = 0; j < 8; j++) bv[j] = bias[n0 + tx * 8 + j];
    #pragma unroll
    for (int i = 0; i < 8; i++) {
        size_t rowoff = (size_t)(m0 + ty * 8 + i) * G4H + n0 + tx * 8;
        #pragma unroll
        for (int j = 0; j < 4; j++) {
            float2 v = up2(acc[i][j]);
            C[rowoff + 2 * j]     = v.x + bv[2 * j];
            C[rowoff + 2 * j + 1] = v.y + bv[2 * j + 1];
        }
    }
}

// ---------------------------------------------------------------------------
// Stage h into hsf[k*HSTR + b]. KROWS rows; src1 covers k<512, src2 the rest.
// ---------------------------------------------------------------------------
template <int KROWS>
__device__ __forceinline__ void stage_h(const float* __restrict__ src1,
                                        const float* __restrict__ src2,
                                        float* hsf) {
    const int tid = threadIdx.x;
    for (int idx = tid; idx < 4 * KROWS; idx += 512) {
        int bb, k;
        if (KROWS == 512) { bb = idx >> 9;  k = idx & 511;  }
        else              { bb = idx >> 10; k = idx & 1023; }
        int b0 = 4 * bb;
        const float* s = (KROWS == 512 || k < 512) ? (src1 + k) : (src2 + (k - 512));
        float4 v;
        v.x = s[(b0 + 0) * PROJ];
        v.y = s[(b0 + 1) * PROJ];
        v.z = s[(b0 + 2) * PROJ];
        v.w = s[(b0 + 3) * PROJ];
        *(float4*)&hsf[k * HSTR + 4 * bb] = v;
    }
}

// ---------------------------------------------------------------------------
// Gate core (staging done by caller): 512 threads, 8-way K split,
// micro-tile 8 rows x 4 batches. c-state in register.
// ---------------------------------------------------------------------------
template <int KTOT>
__device__ __forceinline__ void gate_core(
    const float* __restrict__ Wt, const float* __restrict__ xg,
    float& cref, float* __restrict__ gh, float* __restrict__ cglob, bool last,
    const float* hsf, ulonglong2* redu2, float* zbuf)
{
    const int tid = threadIdx.x;
    const int ksub = tid >> 6;            // 0..7
    const int r    = tid & 63;            // 0..63
    const int rowg = r >> 2;              // 0..15
    const int bg   = (r & 3) << 2;        // 0,4,8,12
    const int gate = rowg >> 2;           // 0..3
    const int j0   = blockIdx.x * 32;
    const int jj   = (rowg & 3) << 3;     // 0,8,16,24
    const int row8 = gate * HID + j0 + jj;
    const int kh   = KTOT / 8;
    const int kbeg = ksub * kh;

    const ulonglong2* wp = (const ulonglong2*)(Wt + (size_t)kbeg * G4H + row8);
    const float* hp = hsf + (size_t)kbeg * HSTR + bg;

    unsigned long long acc[4][4];
    #pragma unroll
    for (int i = 0; i < 4; i++)
        #pragma unroll
        for (int j = 0; j < 4; j++) acc[i][j] = 0ull;

    #pragma unroll 8
    for (int k = 0; k < kh; k++) {
        ulonglong2 wa = wp[(size_t)k * (G4H / 4)];
        ulonglong2 wb = wp[(size_t)k * (G4H / 4) + 1];
        float4 h = *(const float4*)(hp + k * HSTR);
        unsigned long long h0 = pk2(h.x, h.x), h1 = pk2(h.y, h.y);
        unsigned long long h2 = pk2(h.z, h.z), h3 = pk2(h.w, h.w);
        fma2(acc[0][0], wa.x, h0); fma2(acc[0][1], wa.x, h1);
        fma2(acc[0][2], wa.x, h2); fma2(acc[0][3], wa.x, h3);
        fma2(acc[1][0], wa.y, h0); fma2(acc[1][1], wa.y, h1);
        fma2(acc[1][2], wa.y, h2); fma2(acc[1][3], wa.y, h3);
        fma2(acc[2][0], wb.x, h0); fma2(acc[2][1], wb.x, h1);
        fma2(acc[2][2], wb.x, h2); fma2(acc[2][3], wb.x, h3);
        fma2(acc[3][0], wb.y, h0); fma2(acc[3][1], wb.y, h1);
        fma2(acc[3][2], wb.y, h2); fma2(acc[3][3], wb.y, h3);
    }

    if (ksub > 0) {
        ulonglong2* dst = redu2 + (size_t)(ksub - 1) * 512 + r;
        #pragma unroll
        for (int rp = 0; rp < 4; rp++)
            #pragma unroll
            for (int bh = 0; bh < 2; bh++)
                dst[(rp * 2 + bh) * 64] = make_ulonglong2(acc[rp][2 * bh],
                                                          acc[rp][2 * bh + 1]);
    }
    __syncthreads();

    if (ksub == 0) {
        #pragma unroll
        for (int g = 0; g < 7; g++) {
            const ulonglong2* src = redu2 + (size_t)g * 512 + r;
            #pragma unroll
            for (int rp = 0; rp < 4; rp++)
                #pragma unroll
                for (int bh = 0; bh < 2; bh++) {
                    ulonglong2 v = src[(rp * 2 + bh) * 64];
                    acc[rp][2 * bh]     = add2(acc[rp][2 * bh], v.x);
                    acc[rp][2 * bh + 1] = add2(acc[rp][2 * bh + 1], v.y);
                }
        }
        #pragma unroll
        for (int bi = 0; bi < 4; bi++) {
            const float* xr = xg + (size_t)(bg + bi) * G4H + row8;
            float4 x0 = *(const float4*)xr;
            float4 x1 = *(const float4*)(xr + 4);
            float2 a0 = up2(acc[0][bi]), a1 = up2(acc[1][bi]);
            float2 a2 = up2(acc[2][bi]), a3 = up2(acc[3][bi]);
            float4 z0 = {a0.x + x0.x, a0.y + x0.y, a1.x + x0.z, a1.y + x0.w};
            float4 z1 = {a2.x + x1.x, a2.y + x1.y, a3.x + x1.z, a3.y + x1.w};
            float* zb = &zbuf[gate * 512 + (bg + bi) * 32 + jj];
            *(float4*)zb = z0;
            *(float4*)(zb + 4) = z1;
        }
    }
    __syncthreads();

    {
        int b = tid >> 5, jl = tid & 31;
        float zi = zbuf[0 * 512 + b * 32 + jl];
        float zf = zbuf[1 * 512 + b * 32 + jl];
        float zg = zbuf[2 * 512 + b * 32 + jl];
        float zo = zbuf[3 * 512 + b * 32 + jl];
        size_t off = (size_t)b * HID + j0 + jl;
        float cn = sigf(zf) * cref + sigf(zi) * tanhf(zg);
        cref = cn;
        gh[off] = sigf(zo) * tanhf(cn);
        if (last) cglob[off] = cn;
    }
}

// ---------------------------------------------------------------------------
// Proj staging + core. Block covers p-tile (128) x k-chunk (128).
// ---------------------------------------------------------------------------
__device__ __forceinline__ void stage_g(const float* __restrict__ gh,
                                        int kb, float* gpf) {
    const int tid = threadIdx.x;
    int bb = tid >> 7, k = tid & 127;
    int b0 = 4 * bb;
    float4 v;
    v.x = __ldcg(gh + (size_t)(b0 + 0) * HID + kb + k);
    v.y = __ldcg(gh + (size_t)(b0 + 1) * HID + kb + k);
    v.z = __ldcg(gh + (size_t)(b0 + 2) * HID + kb + k);
    v.w = __ldcg(gh + (size_t)(b0 + 3) * HID + kb + k);
    *(float4*)&gpf[k * HSTR + 4 * bb] = v;
}

__device__ __forceinline__ void proj_core(
    const float* gpf, const float* __restrict__ Wtr,
    float* __restrict__ hout, int p0, int kb, unsigned long long* predu)
{
    const int tid = threadIdx.x;
    const int ks = tid >> 7, r = tid & 127;
    const int rowg = r >> 2, bg = (r & 3) << 2;
    const int p4 = p0 + rowg * 4;
    const int kbeg = ks * 32;

    const ulonglong2* wp = (const ulonglong2*)(Wtr + (size_t)(kb + kbeg) * PROJ + p4);
    const float* hp = gpf + kbeg * HSTR + bg;

    unsigned long long acc[2][4];
    #pragma unroll
    for (int i = 0; i < 2; i++)
        #pragma unroll
        for (int j = 0; j < 4; j++) acc[i][j] = 0ull;

    #pragma unroll 8
    for (int k = 0; k < 32; k++) {
        ulonglong2 w = wp[(size_t)k * (PROJ / 4)];
        float4 h = *(const float4*)(hp + k * HSTR);
        unsigned long long h0 = pk2(h.x, h.x), h1 = pk2(h.y, h.y);
        unsigned long long h2 = pk2(h.z, h.z), h3 = pk2(h.w, h.w);
        fma2(acc[0][0], w.x, h0); fma2(acc[1][0], w.y, h0);
        fma2(acc[0][1], w.x, h1); fma2(acc[1][1], w.y, h1);
        fma2(acc[0][2], w.x, h2); fma2(acc[1][2], w.y, h2);
        fma2(acc[0][3], w.x, h3); fma2(acc[1][3], w.y, h3);
    }

    if (ks > 0) {
        unsigned long long* dst = predu + (size_t)(ks - 1) * 1152 + r * 9;
        #pragma unroll
        for (int rp = 0; rp < 2; rp++)
            #pragma unroll
            for (int bi = 0; bi < 4; bi++) dst[rp * 4 + bi] = acc[rp][bi];
    }
    __syncthreads();

    if (ks == 0) {
        #pragma unroll
        for (int g = 0; g < 3; g++) {
            const unsigned long long* src = predu + (size_t)g * 1152 + r * 9;
            #pragma unroll
            for (int rp = 0; rp < 2; rp++)
                #pragma unroll
                for (int bi = 0; bi < 4; bi++)
                    acc[rp][bi] = add2(acc[rp][bi], src[rp * 4 + bi]);
        }
        #pragma unroll
        for (int bi = 0; bi < 4; bi++) {
            float2 a0 = up2(acc[0][bi]);
            float2 a1 = up2(acc[1][bi]);
            float* o = hout + (size_t)(bg + bi) * PROJ + p4;
            atomicAdd(o + 0, a0.x);
            atomicAdd(o + 1, a0.y);
            atomicAdd(o + 2, a1.x);
            atomicAdd(o + 3, a1.y);
        }
    }
}

// ---------------------------------------------------------------------------
// Persistent recurrence with layer pipelining:
//   prologue: G1(0), P1(0)
//   loop t=0..254:  [G1(t+1) ; G2(t)]  |barrier|  [P1(t+1) ; P2(t)]  |barrier|
//   tail: G2(255), P2(255)
// ---------------------------------------------------------------------------
__global__ void __launch_bounds__(512, 1) recurrence_kernel() {
    extern __shared__ float smem[];
    float* hsf  = smem;
    ulonglong2* redu2 = (ulonglong2*)(smem + SM_RED_OFF_F);
    float* zbuf = smem + SM_Z_OFF_F;
    float* gpf1 = smem;
    float* gpf2 = smem + 2560;
    unsigned long long* predu = (unsigned long long*)(smem + 5120);

    const int pt = blockIdx.x & 3;
    const int kc = blockIdx.x >> 2;
    const int p0 = pt * 128, kb = kc * 128;

    unsigned gen = g_genv;
    float c1r = 0.f, c2r = 0.f;

    // prologue: G1(0)
    stage_h<512>(g_out1, nullptr, hsf);
    __syncthreads();
    gate_core<512>(g_Wt1, g_xg1, c1r, g_g1h, g_c1, false, hsf, redu2, zbuf);
    gsync(gen);
    // P1(0) -> out1[1]
    stage_g(g_g1h, kb, gpf1);
    __syncthreads();
    proj_core(gpf1, g_Wtr1, g_out1 + (size_t)1 * (BATCH * PROJ), p0, kb, predu);
    gsync(gen);

    for (int t = 0; t < T_STEPS - 1; t++) {
        // merged gate: G1(t+1) and G2(t); staging shared
        stage_h<1024>(g_out1 + (size_t)(t + 1) * (BATCH * PROJ),
                      g_out2 + (size_t)t * (BATCH * PROJ), hsf);
        __syncthreads();
        gate_core<512>(g_Wt1, g_xg1 + (size_t)(t + 1) * BATCH * G4H,
                       c1r, g_g1h, g_c1, (t + 1 == T_STEPS - 1),
                       hsf, redu2, zbuf);
        __syncthreads();
        gate_core<1024>(g_Wt2, g_xg2 + (size_t)t * BATCH * G4H,
                        c2r, g_g2h, g_c2, false, hsf, redu2, zbuf);
        gsync(gen);
        // merged proj: P1(t+1) -> out1[t+2], P2(t) -> out2[t+1]
        stage_g(g_g1h, kb, gpf1);
        stage_g(g_g2h, kb, gpf2);
        __syncthreads();
        proj_core(gpf1, g_Wtr1, g_out1 + (size_t)(t + 2) * (BATCH * PROJ),
                  p0, kb, predu);
        __syncthreads();
        proj_core(gpf2, g_Wtr2, g_out2 + (size_t)(t + 1) * (BATCH * PROJ),
                  p0, kb, predu);
        gsync(gen);
    }

    // tail: G2(255), P2(255)
    {
        int t = T_STEPS - 1;
        stage_h<1024>(g_out1 + (size_t)(t + 1) * (BATCH * PROJ),
                      g_out2 + (size_t)t * (BATCH * PROJ), hsf);
        __syncthreads();
        gate_core<1024>(g_Wt2, g_xg2 + (size_t)t * BATCH * G4H,
                        c2r, g_g2h, g_c2, true, hsf, redu2, zbuf);
        gsync(gen);
        stage_g(g_g2h, kb, gpf1);
        __syncthreads();
        proj_core(gpf1, g_Wtr2, g_out2 + (size_t)(t + 1) * (BATCH * PROJ),
                  p0, kb, predu);
    }
}

// ---------------------------------------------------------------------------
// Packed-sequence bookkeeping
// ---------------------------------------------------------------------------
__global__ void counts_kernel(const int* __restrict__ lens) {
    int t = threadIdx.x;
    int c = 0;
    #pragma unroll
    for (int b = 0; b < BATCH; b++) c += (lens[b] > t) ? 1 : 0;
    g_counts[t] = c;
    __syncthreads();
    if (t == 0) {
        int s = 0;
        for (int i = 0; i < T_STEPS; i++) { g_offsets[i] = s; s += g_counts[i]; }
        g_offsets[T_STEPS] = s;
    }
}

// ---------------------------------------------------------------------------
// Heads: one warp per packed token
// ---------------------------------------------------------------------------
__global__ void __launch_bounds__(512) heads_kernel(
    const float* __restrict__ Wp, const float* __restrict__ bp,
    const float* __restrict__ Wa, const float* __restrict__ ba,
    float* __restrict__ out, int total) {
    const int t = blockIdx.x;
    const int w = threadIdx.x >> 5;
    const int lane = threadIdx.x & 31;
    if (w >= g_counts[t]) return;
    const int b = w;
    const int tok = g_offsets[t] + b;

    const float* o1 = g_out1 + (size_t)(t + 1) * (BATCH * PROJ) + (size_t)b * PROJ;
    const float* o2 = g_out2 + (size_t)(t + 1) * (BATCH * PROJ) + (size_t)b * PROJ;
    float v[16];
    #pragma unroll
    for (int i = 0; i < 16; i++) v[i] = o1[lane + 32 * i] + o2[lane + 32 * i];

    __shared__ float sp[16][20];
    __shared__ float sa[16][20];
    #pragma unroll
    for (int o = 0; o < 20; o++) {
        float s1 = 0.f, s2 = 0.f;
        #pragma unroll
        for (int i = 0; i < 16; i++) {
            float x = v[i];
            s1 = fmaf(x, Wp[o * PROJ + lane + 32 * i], s1);
            s2 = fmaf(x, Wa[o * PROJ + lane + 32 * i], s2);
        }
        #pragma unroll
        for (int off = 16; off; off >>= 1) {
            s1 += __shfl_xor_sync(0xffffffffu, s1, off);
            s2 += __shfl_xor_sync(0xffffffffu, s2, off);
        }
        if (lane == 0) { sp[w][o] = s1 + bp[o]; sa[w][o] = s2 + ba[o]; }
    }
    __syncwarp();
    if (lane == 0) {
        float m = -1e30f;
        #pragma unroll
        for (int o = 0; o < 20; o++) m = fmaxf(m, sp[w][o]);
        float e[20], sum = 0.f;
        #pragma unroll
        for (int o = 0; o < 20; o++) { e[o] = expf(sp[w][o] - m); sum += e[o]; }
        float inv = 1.f / sum;
        float* aa = out + (size_t)total * 20;
        #pragma unroll
        for (int o = 0; o < 20; o++) {
            out[(size_t)tok * 20 + o] = e[o] * inv;
            aa[(size_t)tok * 20 + o]  = sa[w][o];
        }
    }
}

// ---------------------------------------------------------------------------
// Final states: h1, c1, h2, c2
// ---------------------------------------------------------------------------
__global__ void finalize_kernel(float* __restrict__ out, int total) {
    const size_t base = (size_t)total * 40;
    const int nH = BATCH * PROJ;
    const int nC = BATCH * HID;
    int idx = blockIdx.x * blockDim.x + threadIdx.x;
    if (idx >= 2 * (nH + nC)) return;
    float v;
    if (idx < nH)                v = g_out1[(size_t)T_STEPS * nH + idx];
    else if (idx < nH + nC)      v = g_c1[idx - nH];
    else if (idx < 2 * nH + nC)  v = g_out2[(size_t)T_STEPS * nH + (idx - nH - nC)];
    else                         v = g_c2[idx - 2 * nH - nC];
    out[base + idx] = v;
}

// ---------------------------------------------------------------------------
// Host launch
// ---------------------------------------------------------------------------
extern "C" void kernel_launch(void* const* d_in, const int* in_sizes, int n_in,
                              void* d_out, int out_size) {
    const float* uncon  = (const float*)d_in[0];
    const float* con    = (const float*)d_in[1];
    const int*   lens   = (const int*)d_in[2];
    const float* W_ih1  = (const float*)d_in[3];
    const float* b1     = (const float*)d_in[4];
    const float* W_hh1  = (const float*)d_in[5];
    const float* W_hr1  = (const float*)d_in[6];
    const float* W_ih2  = (const float*)d_in[7];
    const float* b2     = (const float*)d_in[8];
    const float* W_hh2  = (const float*)d_in[9];
    const float* W_hr2  = (const float*)d_in[10];
    const float* W_pssm = (const float*)d_in[11];
    const float* b_pssm = (const float*)d_in[12];
    const float* W_aa   = (const float*)d_in[13];
    const float* b_aa   = (const float*)d_in[14];
    float* out = (float*)d_out;

    const int total = (out_size - 2 * (BATCH * PROJ + BATCH * HID)) / 40;

    float *p_xg1, *p_xg2;
    cudaGetSymbolAddress((void**)&p_xg1, g_xg1);
    cudaGetSymbolAddress((void**)&p_xg2, g_xg2);

    cudaFuncSetAttribute(recurrence_kernel,
                         cudaFuncAttributeMaxDynamicSharedMemorySize, SM_TOTAL_B);

    zero_kernel<<<2048, 256>>>();
    transpose_all<<<28672, dim3(32, 8)>>>(W_hh1, W_ih2, W_hh2, W_hr1, W_hr2);
    sgemm_nt<<<dim3(G4H / 128, (T_STEPS * BATCH) / 128), 256>>>(
        uncon, W_ih1, b1, p_xg1, F1, F1, F1, 0);
    sgemm_nt<<<dim3(G4H / 128, (T_STEPS * BATCH) / 128), 256>>>(
        con, W_ih2, b2, p_xg2, F2CON, F2CON, 1280, 512);
    counts_kernel<<<1, 256>>>(lens);
    recurrence_kernel<<<NBLK, 512, SM_TOTAL_B>>>();
    heads_kernel<<<T_STEPS, 512>>>(W_pssm, b_pssm, W_aa, b_aa, out, total);
    finalize_kernel<<<(2 * (BATCH * PROJ + BATCH * HID) + 255) / 256, 256>>>(out, total);
}